// round 2
// baseline (speedup 1.0000x reference)
#include <cuda_runtime.h>
#include <math.h>

#define BB 8
#define PP 24
#define CC 16
#define DD 256
#define NN 1024
#define KF 13
#define RTOT (BB*NN)      // 8192
#define KCAT (KF*DD)      // 3328

// ---------------- scratch (device globals; no allocations) ----------------
__device__ float g_h[BB*PP*NN*DD];          // (B,P,N,D)      201 MB
__device__ float g_comp[(size_t)KF*RTOT*2*DD]; // (K,R,512)    218 MB
__device__ float g_p1[(size_t)KF*RTOT*DD];  // (K,R,256)      109 MB
__device__ float g_p2[(size_t)RTOT*KCAT];   // (R,3328)       109 MB
__device__ float g_hf1[RTOT*DD];            // (R,256)
__device__ float g_hfreq[RTOT*DD];          // (R,256)
__device__ float g_time_emb[BB*PP*DD];
__device__ float g_periodic[PP*128];
__device__ float g_base_att[PP];
__device__ float g_att[BB*PP];
__device__ float g_dd[BB*4*PP];
__device__ float g_tw[2*KF*PP];

__device__ __forceinline__ float gelu_f(float v) {
    return 0.5f*v*(1.f + erff(v*0.70710678118654752f));
}
__device__ __forceinline__ float softplus_f(float v) {
    return fmaxf(v, 0.f) + log1pf(expf(-fabsf(v)));
}
__device__ void isort(float* a, int n) {
    for (int i = 1; i < n; i++) {
        float v = a[i]; int j = i-1;
        while (j >= 0 && a[j] > v) { a[j+1] = a[j]; j--; }
        a[j+1] = v;
    }
}

// ---------------- tiny init: twiddles, periodic embedding, base_att -------
__global__ void k_init(const float* __restrict__ pe_w1, const float* __restrict__ pe_b1,
                       const float* __restrict__ pe_w2, const float* __restrict__ pe_b2,
                       const float* __restrict__ pool_param)
{
    int t = threadIdx.x;
    for (int idx = t; idx < KF*PP; idx += blockDim.x) {
        int k = idx / PP, p = idx % PP;
        double ang = 2.0*M_PI*(double)(k*p)/24.0;
        g_tw[idx]        = (float)cos(ang);
        g_tw[KF*PP+idx]  = (float)sin(ang);
    }
    if (t < 2*PP) {
        int kk = t / PP, p = t % PP;
        double period = (kk == 0) ? 24.0 : 72.0;
        double ph = 2.0*M_PI*(double)p/period;
        float s = (float)sin(ph), c = (float)cos(ph);
        float hid[64];
        #pragma unroll
        for (int o = 0; o < 64; o++) {
            float v = s*pe_w1[kk*128 + o] + c*pe_w1[kk*128 + 64 + o] + pe_b1[kk*64 + o];
            hid[o] = gelu_f(v);
        }
        for (int q = 0; q < 64; q++) {
            float acc = pe_b2[kk*64 + q];
            #pragma unroll
            for (int o = 0; o < 64; o++) acc += hid[o]*pe_w2[kk*4096 + o*64 + q];
            g_periodic[p*128 + kk*64 + q] = acc;
        }
    }
    if (t == 0) {
        float mx = -1e30f;
        for (int p = 0; p < PP; p++) mx = fmaxf(mx, pool_param[p]);
        float se = 0.f, e[PP];
        for (int p = 0; p < PP; p++) { e[p] = expf(pool_param[p]-mx); se += e[p]; }
        for (int p = 0; p < PP; p++) g_base_att[p] = e[p]/se;
    }
}

// ---------------- spatial mean -> noise; assemble time_emb ----------------
__global__ void k_noise(const float* __restrict__ x, const float* __restrict__ noise_w,
                        const float* __restrict__ noise_b)
{
    int bp = blockIdx.x;       // 0..191 = b*24+p
    int t  = threadIdx.x;      // 256
    __shared__ float partial[256];
    __shared__ float mean[CC];
    const float* xb = x + (size_t)bp*NN*CC;
    float acc = 0.f;
    for (int i = t; i < NN*CC; i += 256) acc += xb[i];   // i%16 == t%16 (256%16==0)
    partial[t] = acc;
    __syncthreads();
    if (t < CC) {
        float s = 0.f;
        for (int j = t; j < 256; j += CC) s += partial[j];
        mean[t] = s*(1.f/(float)NN);
    }
    __syncthreads();
    if (t < 128) {
        float nz = noise_b[t];
        #pragma unroll
        for (int c = 0; c < CC; c++) nz += mean[c]*noise_w[c*128 + t];
        g_time_emb[bp*DD + 128 + t] = nz;
        g_time_emb[bp*DD + t]       = g_periodic[(bp % PP)*128 + t];
    }
}

__global__ void k_timevec(float* __restrict__ out)
{
    int b = blockIdx.x, e = threadIdx.x;
    float s = 0.f;
    for (int p = 0; p < PP; p++) s += g_time_emb[(b*PP + p)*DD + e];
    out[(size_t)BB*NN*DD + b*DD + e] = s*(1.f/24.f);
}

// ---------------- h = x @ Wproj + b + time_emb ----------------------------
__global__ void k_proj(const float* __restrict__ x, const float* __restrict__ w,
                       const float* __restrict__ bias)
{
    int blk = blockIdx.x;      // 0..3071
    int bp  = blk >> 4;
    int n0  = (blk & 15) * 64;
    int t   = threadIdx.x;     // 256
    __shared__ float Ws[CC*DD];
    __shared__ float xs[64*CC];
    __shared__ float tb[DD];
    for (int i = t; i < CC*DD; i += 256) Ws[i] = w[i];
    tb[t] = bias[t] + g_time_emb[bp*DD + t];
    const float* xp = x + ((size_t)bp*NN + n0)*CC;
    for (int i = t; i < 64*CC; i += 256) xs[i] = xp[i];
    __syncthreads();
    float* hp = g_h + ((size_t)bp*NN + n0)*DD;
    for (int nn = 0; nn < 64; nn++) {
        float acc = tb[t];
        #pragma unroll
        for (int c = 0; c < CC; c++) acc += xs[nn*CC + c]*Ws[c*DD + t];
        hp[(size_t)nn*DD + t] = acc;
    }
}

// ---------------- DFT along P (rfft, 13 freqs) ----------------------------
__global__ void k_dft()
{
    int r = blockIdx.x;        // 0..8191 = b*1024+n
    int e = threadIdx.x;       // 256
    __shared__ float tw[2*KF*PP];
    for (int i = e; i < 2*KF*PP; i += 256) tw[i] = g_tw[i];
    __syncthreads();
    int b = r >> 10, n = r & 1023;
    const float* hp = g_h + (size_t)b*PP*NN*DD + (size_t)n*DD + e;
    float v[PP];
    #pragma unroll
    for (int p = 0; p < PP; p++) v[p] = hp[(size_t)p*NN*DD];
    float* cp = g_comp + (size_t)r*2*DD + e;
    for (int k = 0; k < KF; k++) {
        float re = 0.f, im = 0.f;
        #pragma unroll
        for (int p = 0; p < PP; p++) {
            re += v[p]*tw[k*PP + p];
            im -= v[p]*tw[KF*PP + k*PP + p];
        }
        cp[(size_t)k*RTOT*2*DD]      = re;
        cp[(size_t)k*RTOT*2*DD + DD] = im;
    }
}

// ---------------- tiled SGEMM: C = act(A@W + bias), batched over z --------
template<int ACT>
__global__ void __launch_bounds__(256) k_gemm(
    const float* __restrict__ A, const float* __restrict__ W,
    const float* __restrict__ bias, float* __restrict__ C,
    int K, int Nc, int lda, int ldc,
    long sA, long sW, long sB, long sC)
{
    int z = blockIdx.z;
    A += (size_t)z*sA; W += (size_t)z*sW; bias += (size_t)z*sB; C += (size_t)z*sC;
    __shared__ float As[8][128];
    __shared__ float Bs[8][128];
    int t = threadIdx.x;
    int bm = blockIdx.y*128, bn = blockIdx.x*128;
    int tx = t & 15, ty = t >> 4;
    float acc[8][8];
    #pragma unroll
    for (int i = 0; i < 8; i++)
        #pragma unroll
        for (int j = 0; j < 8; j++) acc[i][j] = 0.f;

    int arow = t >> 1, acol = (t & 1)*4;
    int brow = t >> 5, bcol = (t & 31)*4;
    for (int kt = 0; kt < K; kt += 8) {
        float4 av = *(const float4*)&A[(size_t)(bm + arow)*lda + kt + acol];
        As[acol+0][arow] = av.x; As[acol+1][arow] = av.y;
        As[acol+2][arow] = av.z; As[acol+3][arow] = av.w;
        float4 bv = *(const float4*)&W[(size_t)(kt + brow)*Nc + bn + bcol];
        *(float4*)&Bs[brow][bcol] = bv;
        __syncthreads();
        #pragma unroll
        for (int kk = 0; kk < 8; kk++) {
            float4 a0 = *(float4*)&As[kk][ty*8];
            float4 a1 = *(float4*)&As[kk][ty*8 + 4];
            float4 b0 = *(float4*)&Bs[kk][tx*8];
            float4 b1 = *(float4*)&Bs[kk][tx*8 + 4];
            float ar[8] = {a0.x,a0.y,a0.z,a0.w,a1.x,a1.y,a1.z,a1.w};
            float br[8] = {b0.x,b0.y,b0.z,b0.w,b1.x,b1.y,b1.z,b1.w};
            #pragma unroll
            for (int i = 0; i < 8; i++)
                #pragma unroll
                for (int j = 0; j < 8; j++) acc[i][j] += ar[i]*br[j];
        }
        __syncthreads();
    }
    #pragma unroll
    for (int i = 0; i < 8; i++) {
        int row = bm + ty*8 + i;
        #pragma unroll
        for (int j = 0; j < 8; j++) {
            int col = bn + tx*8 + j;
            float v = acc[i][j] + bias[col];
            if (ACT) v = gelu_f(v);
            acc[i][j] = v;
        }
        float4* cp = (float4*)&C[(size_t)row*ldc + bn + tx*8];
        cp[0] = make_float4(acc[i][0], acc[i][1], acc[i][2], acc[i][3]);
        cp[1] = make_float4(acc[i][4], acc[i][5], acc[i][6], acc[i][7]);
    }
}

// ---------------- gating: lagged diffs over raw x -------------------------
__device__ __forceinline__ float xr_val(const float* __restrict__ xb, int p, int i)
{
    float xp = xb[(size_t)p*16384 + i];
    float base;
    if (p <= 1) base = xb[i];
    else base = (xb[(size_t)(p-2)*16384 + i] + xb[(size_t)(p-1)*16384 + i] + xp)*(1.f/3.f);
    return xp - base;
}

__global__ void k_gd(const float* __restrict__ x)
{
    int bp = blockIdx.x;     // 0..191
    int b = bp / PP, p = bp % PP;
    int t = threadIdx.x;     // 256
    const float* xb = x + (size_t)b*PP*16384;
    const int lags[4] = {1, 2, 4, 6};
    float s0=0.f, s1=0.f, s2=0.f, s3=0.f;
    for (int i = t; i < 16384; i += 256) {
        float xr_p = xr_val(xb, p, i);
        if (p >= 1) s0 += fabsf(xr_p - xr_val(xb, p-1, i));
        if (p >= 2) s1 += fabsf(xr_p - xr_val(xb, p-2, i));
        if (p >= 4) s2 += fabsf(xr_p - xr_val(xb, p-4, i));
        if (p >= 6) s3 += fabsf(xr_p - xr_val(xb, p-6, i));
    }
    __shared__ float red[4][256];
    red[0][t]=s0; red[1][t]=s1; red[2][t]=s2; red[3][t]=s3;
    __syncthreads();
    if (t < 4) {
        float ss = 0.f;
        for (int j = 0; j < 256; j++) ss += red[t][j];
        (void)lags;
        g_dd[(b*4 + t)*PP + p] = ss*(1.f/16384.f);
    }
}

__global__ void k_att()
{
    __shared__ float sp[BB][4][PP];
    int t = threadIdx.x;   // 32
    if (t < 32) {
        int b = t >> 2, l = t & 3;
        float dv[PP], srt[PP];
        for (int p = 0; p < PP; p++) dv[p] = g_dd[(b*4 + l)*PP + p];
        for (int p = 0; p < PP; p++) srt[p] = dv[p];
        isort(srt, PP);
        float med = srt[11];
        for (int p = 0; p < PP; p++) srt[p] = fabsf(dv[p] - med);
        isort(srt, PP);
        float mad = srt[11];
        float denom = mad*1.4826f + 1e-6f;
        for (int p = 0; p < PP; p++) {
            float zz = (dv[p] - med)/denom;
            sp[b][l][p] = softplus_f(zz);
        }
    }
    __syncthreads();
    if (t < BB) {
        int b = t;
        float g[PP];
        for (int p = 0; p < PP; p++)
            g[p] = 0.25f*(sp[b][0][p] + sp[b][1][p] + sp[b][2][p] + sp[b][3][p]);
        float c = g[0];
        for (int p = 1; p < PP; p++) { c = 0.6f*c + 0.4f*g[p]; g[p] = c; }
        float gm = 0.f;
        for (int p = 0; p < PP; p++) gm += g[p];
        gm *= (1.f/24.f);
        float logit[PP], mx = -1e30f;
        for (int p = 0; p < PP; p++) {
            float gg = 1.f/(1.f + expf(-1.5f*(g[p] - gm)));
            logit[p] = g_base_att[p]*(1.f + gg);
            mx = fmaxf(mx, logit[p]);
        }
        float se = 0.f;
        for (int p = 0; p < PP; p++) { logit[p] = expf(logit[p] - mx); se += logit[p]; }
        for (int p = 0; p < PP; p++) g_att[b*PP + p] = logit[p]/se;
    }
}

// ---------------- z = sum_p att*h + 0.3*h_freq ----------------------------
__global__ void k_zout(float* __restrict__ out)
{
    int r = blockIdx.x;    // 0..8191
    int e = threadIdx.x;   // 256
    int b = r >> 10, n = r & 1023;
    __shared__ float att[PP];
    if (e < PP) att[e] = g_att[b*PP + e];
    __syncthreads();
    const float* hp = g_h + (size_t)b*PP*NN*DD + (size_t)n*DD + e;
    float acc = 0.3f*g_hfreq[(size_t)r*DD + e];
    #pragma unroll
    for (int p = 0; p < PP; p++) acc += att[p]*hp[(size_t)p*NN*DD];
    out[(size_t)r*DD + e] = acc;
}

// ---------------- launch ---------------------------------------------------
extern "C" void kernel_launch(void* const* d_in, const int* in_sizes, int n_in,
                              void* d_out, int out_size)
{
    const float* x         = (const float*)d_in[0];
    const float* in_proj_w = (const float*)d_in[1];
    const float* in_proj_b = (const float*)d_in[2];
    const float* pe_w1     = (const float*)d_in[3];
    const float* pe_b1     = (const float*)d_in[4];
    const float* pe_w2     = (const float*)d_in[5];
    const float* pe_b2     = (const float*)d_in[6];
    const float* noise_w   = (const float*)d_in[7];
    const float* noise_b   = (const float*)d_in[8];
    const float* sfe_w1    = (const float*)d_in[9];
    const float* sfe_b1    = (const float*)d_in[10];
    const float* sfe_w2    = (const float*)d_in[11];
    const float* sfe_b2    = (const float*)d_in[12];
    const float* comb_w1   = (const float*)d_in[13];
    const float* comb_b1   = (const float*)d_in[14];
    const float* comb_w2   = (const float*)d_in[15];
    const float* comb_b2   = (const float*)d_in[16];
    const float* pool_param= (const float*)d_in[17];
    float* out = (float*)d_out;

    float *p_comp, *p_p1, *p_p2, *p_hf1, *p_hfreq;
    cudaGetSymbolAddress((void**)&p_comp,  g_comp);
    cudaGetSymbolAddress((void**)&p_p1,    g_p1);
    cudaGetSymbolAddress((void**)&p_p2,    g_p2);
    cudaGetSymbolAddress((void**)&p_hf1,   g_hf1);
    cudaGetSymbolAddress((void**)&p_hfreq, g_hfreq);

    k_init<<<1, 256>>>(pe_w1, pe_b1, pe_w2, pe_b2, pool_param);
    k_noise<<<BB*PP, 256>>>(x, noise_w, noise_b);
    k_timevec<<<BB, 256>>>(out);
    k_proj<<<BB*PP*16, 256>>>(x, in_proj_w, in_proj_b);
    k_dft<<<RTOT, 256>>>();

    // sfe layer 1: per-k  (8192 x 512) @ (512 x 256) -> gelu -> p1
    k_gemm<1><<<dim3(2, 64, KF), 256>>>(p_comp, sfe_w1, sfe_b1, p_p1,
        512, 256, 512, 256,
        (long)RTOT*512, (long)512*256, 256L, (long)RTOT*256);
    // sfe layer 2: per-k  (8192 x 256) @ (256 x 256) -> p2 (packed into (R,3328))
    k_gemm<0><<<dim3(2, 64, KF), 256>>>(p_p1, sfe_w2, sfe_b2, p_p2,
        256, 256, 256, KCAT,
        (long)RTOT*256, (long)256*256, 256L, 256L);
    // combine layer 1: (8192 x 3328) @ (3328 x 256) -> gelu
    k_gemm<1><<<dim3(2, 64, 1), 256>>>(p_p2, comb_w1, comb_b1, p_hf1,
        KCAT, 256, KCAT, 256, 0L, 0L, 0L, 0L);
    // combine layer 2: (8192 x 256) @ (256 x 256)
    k_gemm<0><<<dim3(2, 64, 1), 256>>>(p_hf1, comb_w2, comb_b2, p_hfreq,
        256, 256, 256, 256, 0L, 0L, 0L, 0L);

    k_gd<<<BB*PP, 256>>>(x);
    k_att<<<1, 32>>>();
    k_zout<<<RTOT, 256>>>(out);
}

// round 6
// speedup vs baseline: 1.8687x; 1.8687x over previous
#include <cuda_runtime.h>
#include <cstdint>
#include <math.h>

#define BB 8
#define PP 24
#define CC 16
#define DD 256
#define NN 1024
#define KF 13
#define RTOT (BB*NN)      // 8192
#define KCAT (KF*DD)      // 3328

// ---------------- scratch (device globals; no allocations) ----------------
__device__ __align__(128) float g_h[BB*PP*NN*DD];             // (B,P,N,D)
__device__ __align__(128) float g_comp[(size_t)KF*RTOT*2*DD]; // (K,R,512)
__device__ __align__(128) float g_p1[(size_t)KF*RTOT*DD];     // (K,R,256)
__device__ __align__(128) float g_p2[(size_t)RTOT*KCAT];      // (R,3328)
__device__ __align__(128) float g_hf1[RTOT*DD];
__device__ __align__(128) float g_hfreq[RTOT*DD];
__device__ __align__(128) float g_time_emb[BB*PP*DD];
__device__ __align__(128) float g_periodic[PP*128];
__device__ float g_base_att[PP];
__device__ float g_att[BB*PP];
__device__ float g_dd[BB*4*PP];
__device__ float g_tw[2*KF*PP];
// transposed (K-major) weights
__device__ __align__(128) float g_wt_sfe1[KF*256*512];
__device__ __align__(128) float g_wt_sfe2[KF*256*256];
__device__ __align__(128) float g_wt_comb1[256*KCAT];
__device__ __align__(128) float g_wt_comb2[256*256];

__device__ __forceinline__ float gelu_f(float v) {
    return 0.5f*v*(1.f + erff(v*0.70710678118654752f));
}
__device__ __forceinline__ float softplus_f(float v) {
    return fmaxf(v, 0.f) + log1pf(expf(-fabsf(v)));
}
__device__ void isort(float* a, int n) {
    for (int i = 1; i < n; i++) {
        float v = a[i]; int j = i-1;
        while (j >= 0 && a[j] > v) { a[j+1] = a[j]; j--; }
        a[j+1] = v;
    }
}
__device__ __forceinline__ float tf32r(float x) {
    uint32_t r;
    asm("cvt.rna.tf32.f32 %0, %1;" : "=r"(r) : "f"(x));
    return __uint_as_float(r);
}

// ---------------- warp mma m16n8k8 tf32 ------------------------------------
__device__ __forceinline__ void mma_tf32(float* d, const float4& a, const float2& b) {
    asm volatile("mma.sync.aligned.m16n8k8.row.col.f32.tf32.tf32.f32 "
        "{%0,%1,%2,%3}, {%4,%5,%6,%7}, {%8,%9}, {%0,%1,%2,%3};"
        : "+f"(d[0]), "+f"(d[1]), "+f"(d[2]), "+f"(d[3])
        : "r"(__float_as_uint(a.x)), "r"(__float_as_uint(a.y)),
          "r"(__float_as_uint(a.z)), "r"(__float_as_uint(a.w)),
          "r"(__float_as_uint(b.x)), "r"(__float_as_uint(b.y)));
}

// ---------------- weight transpose [K,N] -> [N,K] --------------------------
__global__ void k_tr(const float* __restrict__ W, float* __restrict__ WT, int K, int N)
{
    __shared__ float tile[32][33];
    int z = blockIdx.z;
    W  += (size_t)z*K*N;
    WT += (size_t)z*K*N;
    int k0 = blockIdx.y*32, n0 = blockIdx.x*32;
    int tx = threadIdx.x, ty = threadIdx.y;
    for (int i = ty; i < 32; i += 8) tile[i][tx] = W[(size_t)(k0+i)*N + n0+tx];
    __syncthreads();
    for (int i = ty; i < 32; i += 8) WT[(size_t)(n0+i)*K + k0+tx] = tile[tx][i];
}

// ---------------- tensor-core GEMM: C[M,256] = act(A[M,K] @ Wt[256,K]^T + b)
// CTA tile 128x128, 8 warps (4 row x 2 col), warp tile 32x64.
// SMEM holds fragment-permuted tf32 chunks (K-chunk = 32).
// A fragment layout per 16x8 tile t: sa[(t*32 + lane)*4 + j], j = posK*2 + posM
//   lane = (row&7)*4 + (k&3), posM = (row>>3)&1, posK = (k>>2)&1
// B fragment layout per 8x8 tile t:  sb[(t*32 + lane)*2 + posK]
//   lane = (n&7)*4 + (k&3), posK = (k>>2)&1
template<int ACT>
__global__ void __launch_bounds__(256) k_mma(
    const float* __restrict__ A, const float* __restrict__ Wt,
    const float* __restrict__ bias, float* __restrict__ C,
    int K, int ldc, long sA, long sW, long sB, long sC)
{
    __shared__ float sa[4096];   // A 128x32, permuted
    __shared__ float sb[4096];   // B 128x32, permuted
    int z = blockIdx.z;
    A    += (size_t)z*sA;
    Wt   += (size_t)z*sW;
    bias += (size_t)z*sB;
    C    += (size_t)z*sC;
    int bm = blockIdx.y*128, bn = blockIdx.x*128;
    int tid = threadIdx.x, wid = tid >> 5, lane = tid & 31;
    int g = lane >> 2, tig = lane & 3;
    int wm = (wid & 3)*32;     // warp row offset
    int wn = (wid >> 2)*64;    // warp col offset

    float acc[2][8][4];
    #pragma unroll
    for (int i = 0; i < 2; i++)
        #pragma unroll
        for (int j = 0; j < 8; j++)
            #pragma unroll
            for (int q = 0; q < 4; q++) acc[i][j][q] = 0.f;

    // per-thread staging: 4 float4 each for A and B
    // f = tid + q*256 in [0,1024): row = f>>3, seg = f&7 (k = seg*4 + e)
    int nch = K >> 5;
    float4 ra[4], rb[4];

    {   // preload chunk 0
        #pragma unroll
        for (int q = 0; q < 4; q++) {
            int f = tid + q*256;
            int row = f >> 3, seg = f & 7;
            ra[q] = *(const float4*)(A  + (size_t)(bm + row)*K + seg*4);
            rb[q] = *(const float4*)(Wt + (size_t)(bn + row)*K + seg*4);
        }
    }

    for (int c = 0; c < nch; c++) {
        // scatter regs -> permuted smem (with tf32 rounding)
        #pragma unroll
        for (int q = 0; q < 4; q++) {
            int f = tid + q*256;
            int row = f >> 3, seg = f & 7;
            int ks = seg >> 1, posK = seg & 1;
            // A: tile (mt*4+ks), lane = gga*4+e, reg j = posK*2 + posM
            int mt = row >> 4, posM = (row >> 3) & 1, gga = row & 7;
            int abase = ((mt*4 + ks)*32 + gga*4)*4 + posK*2 + posM;
            float av[4] = {ra[q].x, ra[q].y, ra[q].z, ra[q].w};
            #pragma unroll
            for (int e = 0; e < 4; e++) sa[abase + e*4] = tf32r(av[e]);
            // B: tile (nt*4+ks), lane = ggb*4+e, reg j = posK
            int nt = row >> 3, ggb = row & 7;
            int bbase = ((nt*4 + ks)*32 + ggb*4)*2 + posK;
            float bv[4] = {rb[q].x, rb[q].y, rb[q].z, rb[q].w};
            #pragma unroll
            for (int e = 0; e < 4; e++) sb[bbase + e*2] = tf32r(bv[e]);
        }
        __syncthreads();
        if (c + 1 < nch) {
            #pragma unroll
            for (int q = 0; q < 4; q++) {
                int f = tid + q*256;
                int row = f >> 3, seg = f & 7;
                ra[q] = *(const float4*)(A  + (size_t)(bm + row)*K + (c+1)*32 + seg*4);
                rb[q] = *(const float4*)(Wt + (size_t)(bn + row)*K + (c+1)*32 + seg*4);
            }
        }
        #pragma unroll
        for (int ks = 0; ks < 4; ks++) {
            float4 af[2];
            #pragma unroll
            for (int i = 0; i < 2; i++) {
                int mt = (wid & 3)*2 + i;
                af[i] = *(const float4*)&sa[((mt*4 + ks)*32 + lane)*4];
            }
            float2 bf[8];
            #pragma unroll
            for (int j = 0; j < 8; j++) {
                int nt = (wid >> 2)*8 + j;
                bf[j] = *(const float2*)&sb[((nt*4 + ks)*32 + lane)*2];
            }
            #pragma unroll
            for (int i = 0; i < 2; i++)
                #pragma unroll
                for (int j = 0; j < 8; j++)
                    mma_tf32(acc[i][j], af[i], bf[j]);
        }
        __syncthreads();
    }

    // epilogue: c0,c1 -> row g, cols 2*tig,2*tig+1 ; c2,c3 -> row g+8
    #pragma unroll
    for (int i = 0; i < 2; i++) {
        int r0 = bm + wm + i*16 + g;
        #pragma unroll
        for (int j = 0; j < 8; j++) {
            int col = bn + wn + j*8 + tig*2;
            float b0 = bias[col], b1 = bias[col+1];
            float v0 = acc[i][j][0] + b0, v1 = acc[i][j][1] + b1;
            float v2 = acc[i][j][2] + b0, v3 = acc[i][j][3] + b1;
            if (ACT) { v0 = gelu_f(v0); v1 = gelu_f(v1); v2 = gelu_f(v2); v3 = gelu_f(v3); }
            *(float2*)(C + (size_t)r0*ldc + col)     = make_float2(v0, v1);
            *(float2*)(C + (size_t)(r0+8)*ldc + col) = make_float2(v2, v3);
        }
    }
}

// ---------------- tiny init: twiddles, periodic embedding, base_att -------
__global__ void k_init(const float* __restrict__ pe_w1, const float* __restrict__ pe_b1,
                       const float* __restrict__ pe_w2, const float* __restrict__ pe_b2,
                       const float* __restrict__ pool_param)
{
    int t = threadIdx.x;
    for (int idx = t; idx < KF*PP; idx += blockDim.x) {
        int k = idx / PP, p = idx % PP;
        double ang = 2.0*M_PI*(double)(k*p)/24.0;
        g_tw[idx]        = (float)cos(ang);
        g_tw[KF*PP+idx]  = (float)sin(ang);
    }
    if (t < 2*PP) {
        int kk = t / PP, p = t % PP;
        double period = (kk == 0) ? 24.0 : 72.0;
        double ph = 2.0*M_PI*(double)p/period;
        float s = (float)sin(ph), c = (float)cos(ph);
        float hid[64];
        #pragma unroll
        for (int o = 0; o < 64; o++) {
            float v = s*pe_w1[kk*128 + o] + c*pe_w1[kk*128 + 64 + o] + pe_b1[kk*64 + o];
            hid[o] = gelu_f(v);
        }
        for (int q = 0; q < 64; q++) {
            float acc = pe_b2[kk*64 + q];
            #pragma unroll
            for (int o = 0; o < 64; o++) acc += hid[o]*pe_w2[kk*4096 + o*64 + q];
            g_periodic[p*128 + kk*64 + q] = acc;
        }
    }
    if (t == 0) {
        float mx = -1e30f;
        for (int p = 0; p < PP; p++) mx = fmaxf(mx, pool_param[p]);
        float se = 0.f, e[PP];
        for (int p = 0; p < PP; p++) { e[p] = expf(pool_param[p]-mx); se += e[p]; }
        for (int p = 0; p < PP; p++) g_base_att[p] = e[p]/se;
    }
}

// ---------------- spatial mean -> noise; assemble time_emb ----------------
__global__ void k_noise(const float* __restrict__ x, const float* __restrict__ noise_w,
                        const float* __restrict__ noise_b)
{
    int bp = blockIdx.x;
    int t  = threadIdx.x;
    __shared__ float partial[256];
    __shared__ float mean[CC];
    const float* xb = x + (size_t)bp*NN*CC;
    float acc = 0.f;
    for (int i = t; i < NN*CC; i += 256) acc += xb[i];
    partial[t] = acc;
    __syncthreads();
    if (t < CC) {
        float s = 0.f;
        for (int j = t; j < 256; j += CC) s += partial[j];
        mean[t] = s*(1.f/(float)NN);
    }
    __syncthreads();
    if (t < 128) {
        float nz = noise_b[t];
        #pragma unroll
        for (int c = 0; c < CC; c++) nz += mean[c]*noise_w[c*128 + t];
        g_time_emb[bp*DD + 128 + t] = nz;
        g_time_emb[bp*DD + t]       = g_periodic[(bp % PP)*128 + t];
    }
}

__global__ void k_timevec(float* __restrict__ out)
{
    int b = blockIdx.x, e = threadIdx.x;
    float s = 0.f;
    for (int p = 0; p < PP; p++) s += g_time_emb[(b*PP + p)*DD + e];
    out[(size_t)BB*NN*DD + b*DD + e] = s*(1.f/24.f);
}

// ---------------- h = x @ Wproj + b + time_emb ----------------------------
__global__ void k_proj(const float* __restrict__ x, const float* __restrict__ w,
                       const float* __restrict__ bias)
{
    int blk = blockIdx.x;
    int bp  = blk >> 4;
    int n0  = (blk & 15) * 64;
    int t   = threadIdx.x;
    __shared__ float Ws[CC*DD];
    __shared__ float xs[64*CC];
    __shared__ float tb[DD];
    for (int i = t; i < CC*DD; i += 256) Ws[i] = w[i];
    tb[t] = bias[t] + g_time_emb[bp*DD + t];
    const float* xp = x + ((size_t)bp*NN + n0)*CC;
    for (int i = t; i < 64*CC; i += 256) xs[i] = xp[i];
    __syncthreads();
    float* hp = g_h + ((size_t)bp*NN + n0)*DD;
    for (int nn = 0; nn < 64; nn++) {
        float acc = tb[t];
        #pragma unroll
        for (int c = 0; c < CC; c++) acc += xs[nn*CC + c]*Ws[c*DD + t];
        hp[(size_t)nn*DD + t] = acc;
    }
}

// ---------------- DFT along P (rfft, 13 freqs) ----------------------------
__global__ void k_dft()
{
    int r = blockIdx.x;
    int e = threadIdx.x;
    __shared__ float tw[2*KF*PP];
    for (int i = e; i < 2*KF*PP; i += 256) tw[i] = g_tw[i];
    __syncthreads();
    int b = r >> 10, n = r & 1023;
    const float* hp = g_h + (size_t)b*PP*NN*DD + (size_t)n*DD + e;
    float v[PP];
    #pragma unroll
    for (int p = 0; p < PP; p++) v[p] = hp[(size_t)p*NN*DD];
    float* cp = g_comp + (size_t)r*2*DD + e;
    for (int k = 0; k < KF; k++) {
        float re = 0.f, im = 0.f;
        #pragma unroll
        for (int p = 0; p < PP; p++) {
            re += v[p]*tw[k*PP + p];
            im -= v[p]*tw[KF*PP + k*PP + p];
        }
        cp[(size_t)k*RTOT*2*DD]      = re;
        cp[(size_t)k*RTOT*2*DD + DD] = im;
    }
}

// ---------------- gating: lagged diffs over raw x -------------------------
__device__ __forceinline__ float xr_val(const float* __restrict__ xb, int p, int i)
{
    float xp = xb[(size_t)p*16384 + i];
    float base;
    if (p <= 1) base = xb[i];
    else base = (xb[(size_t)(p-2)*16384 + i] + xb[(size_t)(p-1)*16384 + i] + xp)*(1.f/3.f);
    return xp - base;
}

__global__ void k_gd(const float* __restrict__ x)
{
    int bp = blockIdx.x;
    int b = bp / PP, p = bp % PP;
    int t = threadIdx.x;
    const float* xb = x + (size_t)b*PP*16384;
    float s0=0.f, s1=0.f, s2=0.f, s3=0.f;
    for (int i = t; i < 16384; i += 256) {
        float xr_p = xr_val(xb, p, i);
        if (p >= 1) s0 += fabsf(xr_p - xr_val(xb, p-1, i));
        if (p >= 2) s1 += fabsf(xr_p - xr_val(xb, p-2, i));
        if (p >= 4) s2 += fabsf(xr_p - xr_val(xb, p-4, i));
        if (p >= 6) s3 += fabsf(xr_p - xr_val(xb, p-6, i));
    }
    __shared__ float red[4][256];
    red[0][t]=s0; red[1][t]=s1; red[2][t]=s2; red[3][t]=s3;
    __syncthreads();
    if (t < 4) {
        float ss = 0.f;
        for (int j = 0; j < 256; j++) ss += red[t][j];
        g_dd[(b*4 + t)*PP + p] = ss*(1.f/16384.f);
    }
}

__global__ void k_att()
{
    __shared__ float sp[BB][4][PP];
    int t = threadIdx.x;
    if (t < 32) {
        int b = t >> 2, l = t & 3;
        float dv[PP], srt[PP];
        for (int p = 0; p < PP; p++) dv[p] = g_dd[(b*4 + l)*PP + p];
        for (int p = 0; p < PP; p++) srt[p] = dv[p];
        isort(srt, PP);
        float med = srt[11];
        for (int p = 0; p < PP; p++) srt[p] = fabsf(dv[p] - med);
        isort(srt, PP);
        float mad = srt[11];
        float denom = mad*1.4826f + 1e-6f;
        for (int p = 0; p < PP; p++) {
            float zz = (dv[p] - med)/denom;
            sp[b][l][p] = softplus_f(zz);
        }
    }
    __syncthreads();
    if (t < BB) {
        int b = t;
        float g[PP];
        for (int p = 0; p < PP; p++)
            g[p] = 0.25f*(sp[b][0][p] + sp[b][1][p] + sp[b][2][p] + sp[b][3][p]);
        float c = g[0];
        for (int p = 1; p < PP; p++) { c = 0.6f*c + 0.4f*g[p]; g[p] = c; }
        float gm = 0.f;
        for (int p = 0; p < PP; p++) gm += g[p];
        gm *= (1.f/24.f);
        float logit[PP], mx = -1e30f;
        for (int p = 0; p < PP; p++) {
            float gg = 1.f/(1.f + expf(-1.5f*(g[p] - gm)));
            logit[p] = g_base_att[p]*(1.f + gg);
            mx = fmaxf(mx, logit[p]);
        }
        float se = 0.f;
        for (int p = 0; p < PP; p++) { logit[p] = expf(logit[p] - mx); se += logit[p]; }
        for (int p = 0; p < PP; p++) g_att[b*PP + p] = logit[p]/se;
    }
}

// ---------------- z = sum_p att*h + 0.3*h_freq ----------------------------
__global__ void k_zout(float* __restrict__ out)
{
    int r = blockIdx.x;
    int e = threadIdx.x;
    int b = r >> 10, n = r & 1023;
    __shared__ float att[PP];
    if (e < PP) att[e] = g_att[b*PP + e];
    __syncthreads();
    const float* hp = g_h + (size_t)b*PP*NN*DD + (size_t)n*DD + e;
    float acc = 0.3f*g_hfreq[(size_t)r*DD + e];
    #pragma unroll
    for (int p = 0; p < PP; p++) acc += att[p]*hp[(size_t)p*NN*DD];
    out[(size_t)r*DD + e] = acc;
}

// ---------------- launch ---------------------------------------------------
extern "C" void kernel_launch(void* const* d_in, const int* in_sizes, int n_in,
                              void* d_out, int out_size)
{
    const float* x         = (const float*)d_in[0];
    const float* in_proj_w = (const float*)d_in[1];
    const float* in_proj_b = (const float*)d_in[2];
    const float* pe_w1     = (const float*)d_in[3];
    const float* pe_b1     = (const float*)d_in[4];
    const float* pe_w2     = (const float*)d_in[5];
    const float* pe_b2     = (const float*)d_in[6];
    const float* noise_w   = (const float*)d_in[7];
    const float* noise_b   = (const float*)d_in[8];
    const float* sfe_w1    = (const float*)d_in[9];
    const float* sfe_b1    = (const float*)d_in[10];
    const float* sfe_w2    = (const float*)d_in[11];
    const float* sfe_b2    = (const float*)d_in[12];
    const float* comb_w1   = (const float*)d_in[13];
    const float* comb_b1   = (const float*)d_in[14];
    const float* comb_w2   = (const float*)d_in[15];
    const float* comb_b2   = (const float*)d_in[16];
    const float* pool_param= (const float*)d_in[17];
    float* out = (float*)d_out;

    float *p_comp, *p_p1, *p_p2, *p_hf1, *p_hfreq;
    float *p_wt1, *p_wt2, *p_wc1, *p_wc2;
    cudaGetSymbolAddress((void**)&p_comp,  g_comp);
    cudaGetSymbolAddress((void**)&p_p1,    g_p1);
    cudaGetSymbolAddress((void**)&p_p2,    g_p2);
    cudaGetSymbolAddress((void**)&p_hf1,   g_hf1);
    cudaGetSymbolAddress((void**)&p_hfreq, g_hfreq);
    cudaGetSymbolAddress((void**)&p_wt1,   g_wt_sfe1);
    cudaGetSymbolAddress((void**)&p_wt2,   g_wt_sfe2);
    cudaGetSymbolAddress((void**)&p_wc1,   g_wt_comb1);
    cudaGetSymbolAddress((void**)&p_wc2,   g_wt_comb2);

    k_init<<<1, 256>>>(pe_w1, pe_b1, pe_w2, pe_b2, pool_param);
    k_noise<<<BB*PP, 256>>>(x, noise_w, noise_b);
    k_timevec<<<BB, 256>>>(out);
    k_proj<<<BB*PP*16, 256>>>(x, in_proj_w, in_proj_b);
    k_dft<<<RTOT, 256>>>();

    // weight transposes to K-major
    dim3 trb(32, 8);
    k_tr<<<dim3(256/32, 512/32, KF),  trb>>>(sfe_w1,  p_wt1, 512, 256);
    k_tr<<<dim3(256/32, 256/32, KF),  trb>>>(sfe_w2,  p_wt2, 256, 256);
    k_tr<<<dim3(256/32, KCAT/32, 1),  trb>>>(comb_w1, p_wc1, KCAT, 256);
    k_tr<<<dim3(256/32, 256/32, 1),   trb>>>(comb_w2, p_wc2, 256, 256);

    // sfe layer 1: per-k (8192 x 512) @ (512 x 256)^T -> gelu -> p1
    k_mma<1><<<dim3(2, 64, KF), 256>>>(p_comp, p_wt1, sfe_b1, p_p1,
        512, 256, (long)RTOT*512, (long)256*512, 256L, (long)RTOT*256);
    // sfe layer 2: per-k (8192 x 256) @ (256 x 256)^T -> p2 (packed into (R,3328))
    k_mma<0><<<dim3(2, 64, KF), 256>>>(p_p1, p_wt2, sfe_b2, p_p2,
        256, KCAT, (long)RTOT*256, (long)256*256, 256L, 256L);
    // combine layer 1: (8192 x 3328) @ (3328 x 256)^T -> gelu
    k_mma<1><<<dim3(2, 64, 1), 256>>>(p_p2, p_wc1, comb_b1, p_hf1,
        KCAT, 256, 0L, 0L, 0L, 0L);
    // combine layer 2: (8192 x 256) @ (256 x 256)^T
    k_mma<0><<<dim3(2, 64, 1), 256>>>(p_hf1, p_wc2, comb_b2, p_hfreq,
        256, 256, 0L, 0L, 0L, 0L);

    k_gd<<<BB*PP, 256>>>(x);
    k_att<<<1, 32>>>();
    k_zout<<<RTOT, 256>>>(out);
}

// round 8
// speedup vs baseline: 1.9724x; 1.0555x over previous
#include <cuda_runtime.h>
#include <cstdint>
#include <math.h>

#define BB 8
#define PP 24
#define CC 16
#define DD 256
#define NN 1024
#define KF 13
#define RTOT (BB*NN)      // 8192

// ---------------- scratch (device globals; no allocations) ----------------
__device__ __align__(128) float g_h[BB*PP*NN*DD];             // (B,P,N,D)
__device__ __align__(128) float g_comp[(size_t)KF*RTOT*2*DD]; // (K,R,512)
__device__ __align__(128) float g_p1[(size_t)KF*RTOT*DD];     // (K,R,256)
__device__ __align__(128) float g_hf1[RTOT*DD];
__device__ __align__(128) float g_zpart[RTOT*DD];
__device__ __align__(128) float g_time_emb[BB*PP*DD];
__device__ __align__(128) float g_periodic[PP*128];
__device__ float g_base_att[PP];
__device__ float g_att[BB*PP];
__device__ float g_dd[BB*4*PP];
__device__ float g_tw[2*KF*PP];
__device__ float g_zero[DD];          // zero-initialized
__device__ float g_bconst[DD];
// transposed / derived weights
__device__ __align__(128) float g_wt_sfe1[KF*256*512];   // K-major sfe_w1
__device__ __align__(128) float g_wc1T[KF*256*256];      // per-k transposed comb_w1 slice
__device__ __align__(128) float g_weffT[KF*256*256];     // WeffT[j][i] = (W2_k@Wc1_k)[i,j]
__device__ __align__(128) float g_wc2T[256*256];         // K-major comb_w2

__device__ __forceinline__ float gelu_f(float v) {
    return 0.5f*v*(1.f + erff(v*0.70710678118654752f));
}
__device__ __forceinline__ float softplus_f(float v) {
    return fmaxf(v, 0.f) + log1pf(expf(-fabsf(v)));
}
__device__ void isort(float* a, int n) {
    for (int i = 1; i < n; i++) {
        float v = a[i]; int j = i-1;
        while (j >= 0 && a[j] > v) { a[j+1] = a[j]; j--; }
        a[j+1] = v;
    }
}
__device__ __forceinline__ float tf32r(float x) {
    uint32_t r;
    asm("cvt.rna.tf32.f32 %0, %1;" : "=r"(r) : "f"(x));
    return __uint_as_float(r);
}

// ---------------- warp mma m16n8k8 tf32 ------------------------------------
__device__ __forceinline__ void mma_tf32(float* d, const float4& a, const float2& b) {
    asm volatile("mma.sync.aligned.m16n8k8.row.col.f32.tf32.tf32.f32 "
        "{%0,%1,%2,%3}, {%4,%5,%6,%7}, {%8,%9}, {%0,%1,%2,%3};"
        : "+f"(d[0]), "+f"(d[1]), "+f"(d[2]), "+f"(d[3])
        : "r"(__float_as_uint(a.x)), "r"(__float_as_uint(a.y)),
          "r"(__float_as_uint(a.z)), "r"(__float_as_uint(a.w)),
          "r"(__float_as_uint(b.x)), "r"(__float_as_uint(b.y)));
}

// GEMM building blocks (CTA tile 128x128, 8 warps, K-chunk 32)
__device__ __forceinline__ void gload(const float* A, const float* Wt, int bm, int bn,
                                      int K, int koff, int tid, float4* ra, float4* rb)
{
    #pragma unroll
    for (int q = 0; q < 4; q++) {
        int f = tid + q*256;
        int row = f >> 3, seg = f & 7;
        ra[q] = *(const float4*)(A  + (size_t)(bm + row)*K + koff + seg*4);
        rb[q] = *(const float4*)(Wt + (size_t)(bn + row)*K + koff + seg*4);
    }
}
__device__ __forceinline__ void gscatter(const float4* ra, const float4* rb,
                                         float* sa, float* sb, int tid)
{
    #pragma unroll
    for (int q = 0; q < 4; q++) {
        int f = tid + q*256;
        int row = f >> 3, seg = f & 7;
        int ks = seg >> 1, posK = seg & 1;
        int mt = row >> 4, posM = (row >> 3) & 1, gga = row & 7;
        int abase = ((mt*4 + ks)*32 + gga*4)*4 + posK*2 + posM;
        float av[4] = {ra[q].x, ra[q].y, ra[q].z, ra[q].w};
        #pragma unroll
        for (int e = 0; e < 4; e++) sa[abase + e*4] = tf32r(av[e]);
        int nt = row >> 3, ggb = row & 7;
        int bbase = ((nt*4 + ks)*32 + ggb*4)*2 + posK;
        float bv[4] = {rb[q].x, rb[q].y, rb[q].z, rb[q].w};
        #pragma unroll
        for (int e = 0; e < 4; e++) sb[bbase + e*2] = tf32r(bv[e]);
    }
}
__device__ __forceinline__ void gmma(const float* sa, const float* sb,
                                     int wid, int lane, float acc[2][8][4])
{
    #pragma unroll
    for (int ks = 0; ks < 4; ks++) {
        float4 af[2];
        #pragma unroll
        for (int i = 0; i < 2; i++) {
            int mt = (wid & 3)*2 + i;
            af[i] = *(const float4*)&sa[((mt*4 + ks)*32 + lane)*4];
        }
        float2 bf[8];
        #pragma unroll
        for (int j = 0; j < 8; j++) {
            int nt = (wid >> 2)*8 + j;
            bf[j] = *(const float2*)&sb[((nt*4 + ks)*32 + lane)*2];
        }
        #pragma unroll
        for (int i = 0; i < 2; i++)
            #pragma unroll
            for (int j = 0; j < 8; j++)
                mma_tf32(acc[i][j], af[i], bf[j]);
    }
}

// ---------------- generic GEMM: C = act(A @ Wt^T + bias) -------------------
// FIN=1: C[r,c] = g_zpart[r*ldc+c] + 0.3*(A@Wt^T + bias)
template<int ACT, int FIN>
__global__ void __launch_bounds__(256) k_mma(
    const float* __restrict__ A, const float* __restrict__ Wt,
    const float* __restrict__ bias, float* __restrict__ C,
    int K, int ldc, long sA, long sW, long sB, long sC)
{
    extern __shared__ float smem[];
    float* sa0 = smem;         float* sa1 = smem + 4096;
    float* sb0 = smem + 8192;  float* sb1 = smem + 12288;
    int z = blockIdx.z;
    A    += (size_t)z*sA;
    Wt   += (size_t)z*sW;
    bias += (size_t)z*sB;
    C    += (size_t)z*sC;
    int bm = blockIdx.y*128, bn = blockIdx.x*128;
    int tid = threadIdx.x, wid = tid >> 5, lane = tid & 31;
    int g = lane >> 2, tig = lane & 3;
    int wm = (wid & 3)*32, wn = (wid >> 2)*64;

    float acc[2][8][4];
    #pragma unroll
    for (int i = 0; i < 2; i++)
        #pragma unroll
        for (int j = 0; j < 8; j++)
            #pragma unroll
            for (int q = 0; q < 4; q++) acc[i][j][q] = 0.f;

    int nch = K >> 5;
    float4 ra[4], rb[4];
    gload(A, Wt, bm, bn, K, 0, tid, ra, rb);
    gscatter(ra, rb, sa0, sb0, tid);
    __syncthreads();
    for (int c = 0; c < nch; c++) {
        int buf = c & 1;
        if (c + 1 < nch) gload(A, Wt, bm, bn, K, (c+1)*32, tid, ra, rb);
        gmma(buf ? sa1 : sa0, buf ? sb1 : sb0, wid, lane, acc);
        if (c + 1 < nch) gscatter(ra, rb, buf ? sa0 : sa1, buf ? sb0 : sb1, tid);
        __syncthreads();
    }

    #pragma unroll
    for (int i = 0; i < 2; i++) {
        int r0 = bm + wm + i*16 + g;
        #pragma unroll
        for (int j = 0; j < 8; j++) {
            int col = bn + wn + j*8 + tig*2;
            float b0 = bias[col], b1 = bias[col+1];
            float v0 = acc[i][j][0] + b0, v1 = acc[i][j][1] + b1;
            float v2 = acc[i][j][2] + b0, v3 = acc[i][j][3] + b1;
            if (ACT) { v0 = gelu_f(v0); v1 = gelu_f(v1); v2 = gelu_f(v2); v3 = gelu_f(v3); }
            if (FIN) {
                v0 = g_zpart[(size_t)r0*ldc + col]       + 0.3f*v0;
                v1 = g_zpart[(size_t)r0*ldc + col + 1]   + 0.3f*v1;
                v2 = g_zpart[(size_t)(r0+8)*ldc + col]   + 0.3f*v2;
                v3 = g_zpart[(size_t)(r0+8)*ldc + col+1] + 0.3f*v3;
            }
            *(float2*)(C + (size_t)r0*ldc + col)     = make_float2(v0, v1);
            *(float2*)(C + (size_t)(r0+8)*ldc + col) = make_float2(v2, v3);
        }
    }
}

// ---------------- fused accumulate GEMM over k: hf1 = gelu(Σ_k p1_k@WeffT_k + bconst)
__global__ void __launch_bounds__(256) k_facc()
{
    extern __shared__ float smem[];
    float* sa0 = smem;         float* sa1 = smem + 4096;
    float* sb0 = smem + 8192;  float* sb1 = smem + 12288;
    int bm = blockIdx.y*128, bn = blockIdx.x*128;
    int tid = threadIdx.x, wid = tid >> 5, lane = tid & 31;
    int g = lane >> 2, tig = lane & 3;
    int wm = (wid & 3)*32, wn = (wid >> 2)*64;

    float acc[2][8][4];
    #pragma unroll
    for (int i = 0; i < 2; i++)
        #pragma unroll
        for (int j = 0; j < 8; j++)
            #pragma unroll
            for (int q = 0; q < 4; q++) acc[i][j][q] = 0.f;

    const int NCH = KF*8;   // 13 k's x 8 chunks of 32 over K=256
    float4 ra[4], rb[4];
    gload(g_p1, g_weffT, bm, bn, 256, 0, tid, ra, rb);
    gscatter(ra, rb, sa0, sb0, tid);
    __syncthreads();
    for (int cc = 0; cc < NCH; cc++) {
        int buf = cc & 1;
        if (cc + 1 < NCH) {
            int k = (cc+1) >> 3, c = (cc+1) & 7;
            gload(g_p1 + (size_t)k*RTOT*256, g_weffT + (size_t)k*65536,
                  bm, bn, 256, c*32, tid, ra, rb);
        }
        gmma(buf ? sa1 : sa0, buf ? sb1 : sb0, wid, lane, acc);
        if (cc + 1 < NCH) gscatter(ra, rb, buf ? sa0 : sa1, buf ? sb0 : sb1, tid);
        __syncthreads();
    }

    #pragma unroll
    for (int i = 0; i < 2; i++) {
        int r0 = bm + wm + i*16 + g;
        #pragma unroll
        for (int j = 0; j < 8; j++) {
            int col = bn + wn + j*8 + tig*2;
            float b0 = g_bconst[col], b1 = g_bconst[col+1];
            float2 lo = make_float2(gelu_f(acc[i][j][0] + b0), gelu_f(acc[i][j][1] + b1));
            float2 hi = make_float2(gelu_f(acc[i][j][2] + b0), gelu_f(acc[i][j][3] + b1));
            *(float2*)(g_hf1 + (size_t)r0*256 + col)     = lo;
            *(float2*)(g_hf1 + (size_t)(r0+8)*256 + col) = hi;
        }
    }
}

// ---------------- weight transpose [K,N] -> [N,K] --------------------------
__global__ void k_tr(const float* __restrict__ W, float* __restrict__ WT, int K, int N)
{
    __shared__ float tile[32][33];
    int z = blockIdx.z;
    W  += (size_t)z*K*N;
    WT += (size_t)z*K*N;
    int k0 = blockIdx.y*32, n0 = blockIdx.x*32;
    int tx = threadIdx.x, ty = threadIdx.y;
    for (int i = ty; i < 32; i += 8) tile[i][tx] = W[(size_t)(k0+i)*N + n0+tx];
    __syncthreads();
    for (int i = ty; i < 32; i += 8) WT[(size_t)(n0+i)*K + k0+tx] = tile[tx][i];
}

// ---------------- folded bias: bconst = comb_b1 + Σ b2·Wc1 -----------------
__global__ void k_bconst(const float* __restrict__ comb_b1,
                         const float* __restrict__ sfe_b2,
                         const float* __restrict__ comb_w1)
{
    int j = threadIdx.x;
    float s = comb_b1[j];
    for (int i = 0; i < KF*256; i++) s += sfe_b2[i]*comb_w1[(size_t)i*256 + j];
    g_bconst[j] = s;
}

// ---------------- tiny init ------------------------------------------------
__global__ void k_init(const float* __restrict__ pe_w1, const float* __restrict__ pe_b1,
                       const float* __restrict__ pe_w2, const float* __restrict__ pe_b2,
                       const float* __restrict__ pool_param)
{
    int t = threadIdx.x;
    for (int idx = t; idx < KF*PP; idx += blockDim.x) {
        int k = idx / PP, p = idx % PP;
        double ang = 2.0*M_PI*(double)(k*p)/24.0;
        g_tw[idx]        = (float)cos(ang);
        g_tw[KF*PP+idx]  = (float)sin(ang);
    }
    if (t < 2*PP) {
        int kk = t / PP, p = t % PP;
        double period = (kk == 0) ? 24.0 : 72.0;
        double ph = 2.0*M_PI*(double)p/period;
        float s = (float)sin(ph), c = (float)cos(ph);
        float hid[64];
        #pragma unroll
        for (int o = 0; o < 64; o++) {
            float v = s*pe_w1[kk*128 + o] + c*pe_w1[kk*128 + 64 + o] + pe_b1[kk*64 + o];
            hid[o] = gelu_f(v);
        }
        for (int q = 0; q < 64; q++) {
            float acc = pe_b2[kk*64 + q];
            #pragma unroll
            for (int o = 0; o < 64; o++) acc += hid[o]*pe_w2[kk*4096 + o*64 + q];
            g_periodic[p*128 + kk*64 + q] = acc;
        }
    }
    if (t == 0) {
        float mx = -1e30f;
        for (int p = 0; p < PP; p++) mx = fmaxf(mx, pool_param[p]);
        float se = 0.f, e[PP];
        for (int p = 0; p < PP; p++) { e[p] = expf(pool_param[p]-mx); se += e[p]; }
        for (int p = 0; p < PP; p++) g_base_att[p] = e[p]/se;
    }
}

// ---------------- spatial mean -> noise; assemble time_emb ----------------
__global__ void k_noise(const float* __restrict__ x, const float* __restrict__ noise_w,
                        const float* __restrict__ noise_b)
{
    int bp = blockIdx.x;
    int t  = threadIdx.x;
    __shared__ float partial[256];
    __shared__ float mean[CC];
    const float* xb = x + (size_t)bp*NN*CC;
    float acc = 0.f;
    for (int i = t; i < NN*CC; i += 256) acc += xb[i];
    partial[t] = acc;
    __syncthreads();
    if (t < CC) {
        float s = 0.f;
        for (int j = t; j < 256; j += CC) s += partial[j];
        mean[t] = s*(1.f/(float)NN);
    }
    __syncthreads();
    if (t < 128) {
        float nz = noise_b[t];
        #pragma unroll
        for (int c = 0; c < CC; c++) nz += mean[c]*noise_w[c*128 + t];
        g_time_emb[bp*DD + 128 + t] = nz;
        g_time_emb[bp*DD + t]       = g_periodic[(bp % PP)*128 + t];
    }
}

__global__ void k_timevec(float* __restrict__ out)
{
    int b = blockIdx.x, e = threadIdx.x;
    float s = 0.f;
    for (int p = 0; p < PP; p++) s += g_time_emb[(b*PP + p)*DD + e];
    out[(size_t)BB*NN*DD + b*DD + e] = s*(1.f/24.f);
}

// ---------------- h = x @ Wproj + b + time_emb ----------------------------
__global__ void k_proj(const float* __restrict__ x, const float* __restrict__ w,
                       const float* __restrict__ bias)
{
    int blk = blockIdx.x;
    int bp  = blk >> 4;
    int n0  = (blk & 15) * 64;
    int t   = threadIdx.x;
    __shared__ float Ws[CC*DD];
    __shared__ float xs[64*CC];
    __shared__ float tb[DD];
    for (int i = t; i < CC*DD; i += 256) Ws[i] = w[i];
    tb[t] = bias[t] + g_time_emb[bp*DD + t];
    const float* xp = x + ((size_t)bp*NN + n0)*CC;
    for (int i = t; i < 64*CC; i += 256) xs[i] = xp[i];
    __syncthreads();
    float* hp = g_h + ((size_t)bp*NN + n0)*DD;
    for (int nn = 0; nn < 64; nn++) {
        float acc = tb[t];
        #pragma unroll
        for (int c = 0; c < CC; c++) acc += xs[nn*CC + c]*Ws[c*DD + t];
        hp[(size_t)nn*DD + t] = acc;
    }
}

// ---------------- DFT along P + z-pool partial -----------------------------
__global__ void k_dft()
{
    int r = blockIdx.x;
    int e = threadIdx.x;
    __shared__ float tw[2*KF*PP];
    __shared__ float att[PP];
    int b = r >> 10, n = r & 1023;
    for (int i = e; i < 2*KF*PP; i += 256) tw[i] = g_tw[i];
    if (e < PP) att[e] = g_att[b*PP + e];
    __syncthreads();
    const float* hp = g_h + (size_t)b*PP*NN*DD + (size_t)n*DD + e;
    float v[PP];
    #pragma unroll
    for (int p = 0; p < PP; p++) v[p] = hp[(size_t)p*NN*DD];
    float zp = 0.f;
    #pragma unroll
    for (int p = 0; p < PP; p++) zp += att[p]*v[p];
    g_zpart[(size_t)r*DD + e] = zp;
    float* cp = g_comp + (size_t)r*2*DD + e;
    for (int k = 0; k < KF; k++) {
        float re = 0.f, im = 0.f;
        #pragma unroll
        for (int p = 0; p < PP; p++) {
            re += v[p]*tw[k*PP + p];
            im -= v[p]*tw[KF*PP + k*PP + p];
        }
        cp[(size_t)k*RTOT*2*DD]      = re;
        cp[(size_t)k*RTOT*2*DD + DD] = im;
    }
}

// ---------------- gating: lagged diffs over raw x -------------------------
__device__ __forceinline__ float xr_val(const float* __restrict__ xb, int p, int i)
{
    float xp = xb[(size_t)p*16384 + i];
    float base;
    if (p <= 1) base = xb[i];
    else base = (xb[(size_t)(p-2)*16384 + i] + xb[(size_t)(p-1)*16384 + i] + xp)*(1.f/3.f);
    return xp - base;
}

__global__ void k_gd(const float* __restrict__ x)
{
    int bp = blockIdx.x;
    int b = bp / PP, p = bp % PP;
    int t = threadIdx.x;
    const float* xb = x + (size_t)b*PP*16384;
    float s0=0.f, s1=0.f, s2=0.f, s3=0.f;
    for (int i = t; i < 16384; i += 256) {
        float xr_p = xr_val(xb, p, i);
        if (p >= 1) s0 += fabsf(xr_p - xr_val(xb, p-1, i));
        if (p >= 2) s1 += fabsf(xr_p - xr_val(xb, p-2, i));
        if (p >= 4) s2 += fabsf(xr_p - xr_val(xb, p-4, i));
        if (p >= 6) s3 += fabsf(xr_p - xr_val(xb, p-6, i));
    }
    __shared__ float red[4][256];
    red[0][t]=s0; red[1][t]=s1; red[2][t]=s2; red[3][t]=s3;
    __syncthreads();
    if (t < 4) {
        float ss = 0.f;
        for (int j = 0; j < 256; j++) ss += red[t][j];
        g_dd[(b*4 + t)*PP + p] = ss*(1.f/16384.f);
    }
}

__global__ void k_att()
{
    __shared__ float sp[BB][4][PP];
    int t = threadIdx.x;
    if (t < 32) {
        int b = t >> 2, l = t & 3;
        float dv[PP], srt[PP];
        for (int p = 0; p < PP; p++) dv[p] = g_dd[(b*4 + l)*PP + p];
        for (int p = 0; p < PP; p++) srt[p] = dv[p];
        isort(srt, PP);
        float med = srt[11];
        for (int p = 0; p < PP; p++) srt[p] = fabsf(dv[p] - med);
        isort(srt, PP);
        float mad = srt[11];
        float denom = mad*1.4826f + 1e-6f;
        for (int p = 0; p < PP; p++) {
            float zz = (dv[p] - med)/denom;
            sp[b][l][p] = softplus_f(zz);
        }
    }
    __syncthreads();
    if (t < BB) {
        int b = t;
        float g[PP];
        for (int p = 0; p < PP; p++)
            g[p] = 0.25f*(sp[b][0][p] + sp[b][1][p] + sp[b][2][p] + sp[b][3][p]);
        float c = g[0];
        for (int p = 1; p < PP; p++) { c = 0.6f*c + 0.4f*g[p]; g[p] = c; }
        float gm = 0.f;
        for (int p = 0; p < PP; p++) gm += g[p];
        gm *= (1.f/24.f);
        float logit[PP], mx = -1e30f;
        for (int p = 0; p < PP; p++) {
            float gg = 1.f/(1.f + expf(-1.5f*(g[p] - gm)));
            logit[p] = g_base_att[p]*(1.f + gg);
            mx = fmaxf(mx, logit[p]);
        }
        float se = 0.f;
        for (int p = 0; p < PP; p++) { logit[p] = expf(logit[p] - mx); se += logit[p]; }
        for (int p = 0; p < PP; p++) g_att[b*PP + p] = logit[p]/se;
    }
}

// ---------------- launch ---------------------------------------------------
extern "C" void kernel_launch(void* const* d_in, const int* in_sizes, int n_in,
                              void* d_out, int out_size)
{
    const float* x         = (const float*)d_in[0];
    const float* in_proj_w = (const float*)d_in[1];
    const float* in_proj_b = (const float*)d_in[2];
    const float* pe_w1     = (const float*)d_in[3];
    const float* pe_b1     = (const float*)d_in[4];
    const float* pe_w2     = (const float*)d_in[5];
    const float* pe_b2     = (const float*)d_in[6];
    const float* noise_w   = (const float*)d_in[7];
    const float* noise_b   = (const float*)d_in[8];
    const float* sfe_w1    = (const float*)d_in[9];
    const float* sfe_b1    = (const float*)d_in[10];
    const float* sfe_w2    = (const float*)d_in[11];
    const float* sfe_b2    = (const float*)d_in[12];
    const float* comb_w1   = (const float*)d_in[13];
    const float* comb_b1   = (const float*)d_in[14];
    const float* comb_w2   = (const float*)d_in[15];
    const float* comb_b2   = (const float*)d_in[16];
    const float* pool_param= (const float*)d_in[17];
    float* out = (float*)d_out;

    float *p_comp, *p_p1, *p_hf1;
    float *p_wt1, *p_wc1T, *p_weffT, *p_wc2T, *p_zero;
    cudaGetSymbolAddress((void**)&p_comp,  g_comp);
    cudaGetSymbolAddress((void**)&p_p1,    g_p1);
    cudaGetSymbolAddress((void**)&p_hf1,   g_hf1);
    cudaGetSymbolAddress((void**)&p_wt1,   g_wt_sfe1);
    cudaGetSymbolAddress((void**)&p_wc1T,  g_wc1T);
    cudaGetSymbolAddress((void**)&p_weffT, g_weffT);
    cudaGetSymbolAddress((void**)&p_wc2T,  g_wc2T);
    cudaGetSymbolAddress((void**)&p_zero,  g_zero);

    const int SMEM = 16384*4;   // 64 KB dynamic
    cudaFuncSetAttribute(k_mma<0,0>, cudaFuncAttributeMaxDynamicSharedMemorySize, SMEM);
    cudaFuncSetAttribute(k_mma<1,0>, cudaFuncAttributeMaxDynamicSharedMemorySize, SMEM);
    cudaFuncSetAttribute(k_mma<0,1>, cudaFuncAttributeMaxDynamicSharedMemorySize, SMEM);
    cudaFuncSetAttribute(k_facc,     cudaFuncAttributeMaxDynamicSharedMemorySize, SMEM);

    // independent prep
    k_init<<<1, 256>>>(pe_w1, pe_b1, pe_w2, pe_b2, pool_param);
    k_gd<<<BB*PP, 256>>>(x);
    k_att<<<1, 32>>>();
    k_noise<<<BB*PP, 256>>>(x, noise_w, noise_b);
    k_timevec<<<BB, 256>>>(out);
    k_proj<<<BB*PP*16, 256>>>(x, in_proj_w, in_proj_b);
    k_dft<<<RTOT, 256>>>();

    // weight prep
    dim3 trb(32, 8);
    k_tr<<<dim3(256/32, 512/32, KF), trb>>>(sfe_w1,  p_wt1,  512, 256);
    k_tr<<<dim3(256/32, 256/32, KF), trb>>>(comb_w1, p_wc1T, 256, 256);  // per-k slices
    k_tr<<<dim3(256/32, 256/32, 1),  trb>>>(comb_w2, p_wc2T, 256, 256);
    // WeffT[j,o] = Σ_q Wc1T[j,q] * W2[o,q]
    k_mma<0,0><<<dim3(2, 2, KF), 256, SMEM>>>(p_wc1T, sfe_w2, p_zero, p_weffT,
        256, 256, 65536L, 65536L, 0L, 65536L);
    k_bconst<<<1, 256>>>(comb_b1, sfe_b2, comb_w1);

    // sfe layer 1: per-k (8192 x 512) @ (512 x 256)^T -> gelu -> p1
    k_mma<1,0><<<dim3(2, 64, KF), 256, SMEM>>>(p_comp, p_wt1, sfe_b1, p_p1,
        512, 256, (long)RTOT*512, 131072L, 256L, (long)RTOT*256);
    // folded sfe2*comb1: hf1 = gelu(Σ_k p1_k @ WeffT_k + bconst)
    k_facc<<<dim3(2, 64), 256, SMEM>>>();
    // comb2 + final: out = zpart + 0.3*(hf1 @ Wc2 + b2)
    k_mma<0,1><<<dim3(2, 64), 256, SMEM>>>(p_hf1, p_wc2T, comb_b2, out,
        256, 256, 0L, 0L, 0L, 0L);
}

// round 9
// speedup vs baseline: 2.7176x; 1.3779x over previous
#include <cuda_runtime.h>
#include <cstdint>
#include <math.h>

#define BB 8
#define PP 24
#define CC 16
#define DD 256
#define NN 1024
#define KF 13
#define RTOT (BB*NN)      // 8192

// ---------------- scratch (device globals; no allocations) ----------------
__device__ __align__(128) float g_xc[(size_t)KF*RTOT*32];   // per-k [re(16)|im(16)]
__device__ __align__(128) float g_xatt[RTOT*CC];
__device__ __align__(128) float g_p1[(size_t)KF*RTOT*DD];   // (K,R,256)
__device__ __align__(128) float g_hf1[RTOT*DD];
__device__ __align__(128) float g_zpart[RTOT*DD];
__device__ __align__(128) float g_time_emb[BB*PP*DD];
__device__ __align__(128) float g_periodic[PP*128];
__device__ float g_base_att[PP];
__device__ float g_att[BB*PP];
__device__ float g_dd[BB*4*PP];
__device__ float g_tw[2*KF*PP];
__device__ float g_zero[DD];
__device__ float g_bconst[DD];
__device__ __align__(128) float g_tere[KF*BB*DD];
__device__ __align__(128) float g_teim[KF*BB*DD];
__device__ __align__(128) float g_teatt[BB*DD];
__device__ __align__(128) float g_ckb[KF*BB*DD];
// derived weights
__device__ __align__(128) float g_wp1T[KF*DD*32];     // [(k,o),32] = W@W1 fold, K-major
__device__ __align__(128) float g_wc1T[KF*DD*DD];
__device__ __align__(128) float g_weffT[KF*DD*DD];
__device__ __align__(128) float g_wc2T[DD*DD];

__device__ __forceinline__ float gelu_f(float v) {
    return 0.5f*v*(1.f + erff(v*0.70710678118654752f));
}
__device__ __forceinline__ float softplus_f(float v) {
    return fmaxf(v, 0.f) + log1pf(expf(-fabsf(v)));
}
__device__ void isort(float* a, int n) {
    for (int i = 1; i < n; i++) {
        float v = a[i]; int j = i-1;
        while (j >= 0 && a[j] > v) { a[j+1] = a[j]; j--; }
        a[j+1] = v;
    }
}
__device__ __forceinline__ float tf32r(float x) {
    uint32_t r;
    asm("cvt.rna.tf32.f32 %0, %1;" : "=r"(r) : "f"(x));
    return __uint_as_float(r);
}

// ---------------- warp mma m16n8k8 tf32 ------------------------------------
__device__ __forceinline__ void mma_tf32(float* d, const float4& a, const float2& b) {
    asm volatile("mma.sync.aligned.m16n8k8.row.col.f32.tf32.tf32.f32 "
        "{%0,%1,%2,%3}, {%4,%5,%6,%7}, {%8,%9}, {%0,%1,%2,%3};"
        : "+f"(d[0]), "+f"(d[1]), "+f"(d[2]), "+f"(d[3])
        : "r"(__float_as_uint(a.x)), "r"(__float_as_uint(a.y)),
          "r"(__float_as_uint(a.z)), "r"(__float_as_uint(a.w)),
          "r"(__float_as_uint(b.x)), "r"(__float_as_uint(b.y)));
}

// GEMM building blocks (CTA tile 128x128, 8 warps, K-chunk 32)
__device__ __forceinline__ void gload(const float* A, const float* Wt, int bm, int bn,
                                      int K, int koff, int tid, float4* ra, float4* rb)
{
    #pragma unroll
    for (int q = 0; q < 4; q++) {
        int f = tid + q*256;
        int row = f >> 3, seg = f & 7;
        ra[q] = *(const float4*)(A  + (size_t)(bm + row)*K + koff + seg*4);
        rb[q] = *(const float4*)(Wt + (size_t)(bn + row)*K + koff + seg*4);
    }
}
__device__ __forceinline__ void gscatter(const float4* ra, const float4* rb,
                                         float* sa, float* sb, int tid)
{
    #pragma unroll
    for (int q = 0; q < 4; q++) {
        int f = tid + q*256;
        int row = f >> 3, seg = f & 7;
        int ks = seg >> 1, posK = seg & 1;
        int mt = row >> 4, posM = (row >> 3) & 1, gga = row & 7;
        int abase = ((mt*4 + ks)*32 + gga*4)*4 + posK*2 + posM;
        float av[4] = {ra[q].x, ra[q].y, ra[q].z, ra[q].w};
        #pragma unroll
        for (int e = 0; e < 4; e++) sa[abase + e*4] = tf32r(av[e]);
        int nt = row >> 3, ggb = row & 7;
        int bbase = ((nt*4 + ks)*32 + ggb*4)*2 + posK;
        float bv[4] = {rb[q].x, rb[q].y, rb[q].z, rb[q].w};
        #pragma unroll
        for (int e = 0; e < 4; e++) sb[bbase + e*2] = tf32r(bv[e]);
    }
}
__device__ __forceinline__ void gmma(const float* sa, const float* sb,
                                     int wid, int lane, float acc[2][8][4])
{
    #pragma unroll
    for (int ks = 0; ks < 4; ks++) {
        float4 af[2];
        #pragma unroll
        for (int i = 0; i < 2; i++) {
            int mt = (wid & 3)*2 + i;
            af[i] = *(const float4*)&sa[((mt*4 + ks)*32 + lane)*4];
        }
        float2 bf[8];
        #pragma unroll
        for (int j = 0; j < 8; j++) {
            int nt = (wid >> 2)*8 + j;
            bf[j] = *(const float2*)&sb[((nt*4 + ks)*32 + lane)*2];
        }
        #pragma unroll
        for (int i = 0; i < 2; i++)
            #pragma unroll
            for (int j = 0; j < 8; j++)
                mma_tf32(acc[i][j], af[i], bf[j]);
    }
}

// ---------------- generic GEMM: C = act(A @ Wt^T + bias) -------------------
// FIN=1: C = g_zpart + 0.3*(...). bstride: per-batch bias stride (rows/batch=1024)
template<int ACT, int FIN>
__global__ void __launch_bounds__(256) k_mma(
    const float* __restrict__ A, const float* __restrict__ Wt,
    const float* __restrict__ bias, float* __restrict__ C,
    int K, int ldc, long sA, long sW, long sB, long sC, int bstride)
{
    extern __shared__ float smem[];
    float* sa0 = smem;         float* sa1 = smem + 4096;
    float* sb0 = smem + 8192;  float* sb1 = smem + 12288;
    int z = blockIdx.z;
    int bm = blockIdx.y*128, bn = blockIdx.x*128;
    A    += (size_t)z*sA;
    Wt   += (size_t)z*sW;
    bias += (size_t)z*sB + (size_t)(bm >> 10)*bstride;
    C    += (size_t)z*sC;
    int tid = threadIdx.x, wid = tid >> 5, lane = tid & 31;
    int g = lane >> 2, tig = lane & 3;
    int wm = (wid & 3)*32, wn = (wid >> 2)*64;

    float acc[2][8][4];
    #pragma unroll
    for (int i = 0; i < 2; i++)
        #pragma unroll
        for (int j = 0; j < 8; j++)
            #pragma unroll
            for (int q = 0; q < 4; q++) acc[i][j][q] = 0.f;

    int nch = K >> 5;
    float4 ra[4], rb[4];
    gload(A, Wt, bm, bn, K, 0, tid, ra, rb);
    gscatter(ra, rb, sa0, sb0, tid);
    __syncthreads();
    for (int c = 0; c < nch; c++) {
        int buf = c & 1;
        if (c + 1 < nch) gload(A, Wt, bm, bn, K, (c+1)*32, tid, ra, rb);
        gmma(buf ? sa1 : sa0, buf ? sb1 : sb0, wid, lane, acc);
        if (c + 1 < nch) gscatter(ra, rb, buf ? sa0 : sa1, buf ? sb0 : sb1, tid);
        __syncthreads();
    }

    #pragma unroll
    for (int i = 0; i < 2; i++) {
        int r0 = bm + wm + i*16 + g;
        #pragma unroll
        for (int j = 0; j < 8; j++) {
            int col = bn + wn + j*8 + tig*2;
            float b0 = bias[col], b1 = bias[col+1];
            float v0 = acc[i][j][0] + b0, v1 = acc[i][j][1] + b1;
            float v2 = acc[i][j][2] + b0, v3 = acc[i][j][3] + b1;
            if (ACT) { v0 = gelu_f(v0); v1 = gelu_f(v1); v2 = gelu_f(v2); v3 = gelu_f(v3); }
            if (FIN) {
                v0 = g_zpart[(size_t)r0*ldc + col]       + 0.3f*v0;
                v1 = g_zpart[(size_t)r0*ldc + col + 1]   + 0.3f*v1;
                v2 = g_zpart[(size_t)(r0+8)*ldc + col]   + 0.3f*v2;
                v3 = g_zpart[(size_t)(r0+8)*ldc + col+1] + 0.3f*v3;
            }
            *(float2*)(C + (size_t)r0*ldc + col)     = make_float2(v0, v1);
            *(float2*)(C + (size_t)(r0+8)*ldc + col) = make_float2(v2, v3);
        }
    }
}

// ---------------- fused accumulate GEMM over k: hf1 = gelu(Σ_k p1_k@WeffT_k + bconst)
__global__ void __launch_bounds__(256) k_facc()
{
    extern __shared__ float smem[];
    float* sa0 = smem;         float* sa1 = smem + 4096;
    float* sb0 = smem + 8192;  float* sb1 = smem + 12288;
    int bm = blockIdx.y*128, bn = blockIdx.x*128;
    int tid = threadIdx.x, wid = tid >> 5, lane = tid & 31;
    int g = lane >> 2, tig = lane & 3;
    int wm = (wid & 3)*32, wn = (wid >> 2)*64;

    float acc[2][8][4];
    #pragma unroll
    for (int i = 0; i < 2; i++)
        #pragma unroll
        for (int j = 0; j < 8; j++)
            #pragma unroll
            for (int q = 0; q < 4; q++) acc[i][j][q] = 0.f;

    const int NCH = KF*8;
    float4 ra[4], rb[4];
    gload(g_p1, g_weffT, bm, bn, 256, 0, tid, ra, rb);
    gscatter(ra, rb, sa0, sb0, tid);
    __syncthreads();
    for (int cc = 0; cc < NCH; cc++) {
        int buf = cc & 1;
        if (cc + 1 < NCH) {
            int k = (cc+1) >> 3, c = (cc+1) & 7;
            gload(g_p1 + (size_t)k*RTOT*256, g_weffT + (size_t)k*65536,
                  bm, bn, 256, c*32, tid, ra, rb);
        }
        gmma(buf ? sa1 : sa0, buf ? sb1 : sb0, wid, lane, acc);
        if (cc + 1 < NCH) gscatter(ra, rb, buf ? sa0 : sa1, buf ? sb0 : sb1, tid);
        __syncthreads();
    }

    #pragma unroll
    for (int i = 0; i < 2; i++) {
        int r0 = bm + wm + i*16 + g;
        #pragma unroll
        for (int j = 0; j < 8; j++) {
            int col = bn + wn + j*8 + tig*2;
            float b0 = g_bconst[col], b1 = g_bconst[col+1];
            float2 lo = make_float2(gelu_f(acc[i][j][0] + b0), gelu_f(acc[i][j][1] + b1));
            float2 hi = make_float2(gelu_f(acc[i][j][2] + b0), gelu_f(acc[i][j][3] + b1));
            *(float2*)(g_hf1 + (size_t)r0*256 + col)     = lo;
            *(float2*)(g_hf1 + (size_t)(r0+8)*256 + col) = hi;
        }
    }
}

// ---------------- weight transpose [K,N] -> [N,K] --------------------------
__global__ void k_tr(const float* __restrict__ W, float* __restrict__ WT, int K, int N)
{
    __shared__ float tile[32][33];
    int z = blockIdx.z;
    W  += (size_t)z*K*N;
    WT += (size_t)z*K*N;
    int k0 = blockIdx.y*32, n0 = blockIdx.x*32;
    int tx = threadIdx.x, ty = threadIdx.y;
    for (int i = ty; i < 32; i += 8) tile[i][tx] = W[(size_t)(k0+i)*N + n0+tx];
    __syncthreads();
    for (int i = ty; i < 32; i += 8) WT[(size_t)(n0+i)*K + k0+tx] = tile[tx][i];
}

// ---------------- folded weights: wp1T[k][o][c<16]=Σ_e W[c][e]W1_k[e][o] ----
__global__ void k_uv(const float* __restrict__ W, const float* __restrict__ W1)
{
    int k = blockIdx.x, o = threadIdx.x;
    __shared__ float Ws[CC*DD];
    for (int i = o; i < CC*DD; i += 256) Ws[i] = W[i];
    __syncthreads();
    float acc[32];
    #pragma unroll
    for (int c = 0; c < 32; c++) acc[c] = 0.f;
    const float* w1 = W1 + (size_t)k*512*DD;
    for (int e = 0; e < 256; e++) {
        float u = w1[(size_t)e*DD + o];
        float v = w1[(size_t)(256+e)*DD + o];
        #pragma unroll
        for (int c = 0; c < 16; c++) {
            acc[c]      += Ws[c*DD + e]*u;
            acc[16 + c] += Ws[c*DD + e]*v;
        }
    }
    float* dst = g_wp1T + ((size_t)k*DD + o)*32;
    #pragma unroll
    for (int c = 0; c < 32; c++) dst[c] = acc[c];
}

// ---------------- te DFT + te_att ------------------------------------------
__global__ void k_tedft(const float* __restrict__ in_proj_b,
                        const float* __restrict__ att_dummy)
{
    int b = blockIdx.x, e = threadIdx.x;
    float teb[PP];
    #pragma unroll
    for (int p = 0; p < PP; p++)
        teb[p] = g_time_emb[(b*PP + p)*DD + e] + in_proj_b[e];
    float ta = 0.f;
    #pragma unroll
    for (int p = 0; p < PP; p++) ta += g_att[b*PP + p]*teb[p];
    g_teatt[b*DD + e] = ta;
    for (int k = 0; k < KF; k++) {
        float re = 0.f, im = 0.f;
        #pragma unroll
        for (int p = 0; p < PP; p++) {
            re += teb[p]*g_tw[k*PP + p];
            im -= teb[p]*g_tw[KF*PP + k*PP + p];
        }
        g_tere[(k*BB + b)*DD + e] = re;
        g_teim[(k*BB + b)*DD + e] = im;
    }
}

// ---------------- c_kb[o] = b1_k[o] + Σ_e tere*W1_k[e][o] + teim*W1_k[256+e][o]
__global__ void k_ckb(const float* __restrict__ W1, const float* __restrict__ b1)
{
    int k = blockIdx.x, b = blockIdx.y, o = threadIdx.x;
    __shared__ float sre[DD], sim[DD];
    sre[o] = g_tere[(k*BB + b)*DD + o];
    sim[o] = g_teim[(k*BB + b)*DD + o];
    __syncthreads();
    float acc = b1[(size_t)k*DD + o];
    const float* w1 = W1 + (size_t)k*512*DD;
    for (int e = 0; e < 256; e++)
        acc += sre[e]*w1[(size_t)e*DD + o] + sim[e]*w1[(size_t)(256+e)*DD + o];
    g_ckb[(k*BB + b)*DD + o] = acc;
}

// ---------------- folded bias: bconst = comb_b1 + Σ b2·Wc1 -----------------
__global__ void k_bconst(const float* __restrict__ comb_b1,
                         const float* __restrict__ sfe_b2,
                         const float* __restrict__ comb_w1)
{
    int j = threadIdx.x;
    float s = comb_b1[j];
    for (int i = 0; i < KF*256; i++) s += sfe_b2[i]*comb_w1[(size_t)i*256 + j];
    g_bconst[j] = s;
}

// ---------------- tiny init ------------------------------------------------
__global__ void k_init(const float* __restrict__ pe_w1, const float* __restrict__ pe_b1,
                       const float* __restrict__ pe_w2, const float* __restrict__ pe_b2,
                       const float* __restrict__ pool_param)
{
    int t = threadIdx.x;
    for (int idx = t; idx < KF*PP; idx += blockDim.x) {
        int k = idx / PP, p = idx % PP;
        double ang = 2.0*M_PI*(double)(k*p)/24.0;
        g_tw[idx]        = (float)cos(ang);
        g_tw[KF*PP+idx]  = (float)sin(ang);
    }
    if (t < 2*PP) {
        int kk = t / PP, p = t % PP;
        double period = (kk == 0) ? 24.0 : 72.0;
        double ph = 2.0*M_PI*(double)p/period;
        float s = (float)sin(ph), c = (float)cos(ph);
        float hid[64];
        #pragma unroll
        for (int o = 0; o < 64; o++) {
            float v = s*pe_w1[kk*128 + o] + c*pe_w1[kk*128 + 64 + o] + pe_b1[kk*64 + o];
            hid[o] = gelu_f(v);
        }
        for (int q = 0; q < 64; q++) {
            float acc = pe_b2[kk*64 + q];
            #pragma unroll
            for (int o = 0; o < 64; o++) acc += hid[o]*pe_w2[kk*4096 + o*64 + q];
            g_periodic[p*128 + kk*64 + q] = acc;
        }
    }
    if (t == 0) {
        float mx = -1e30f;
        for (int p = 0; p < PP; p++) mx = fmaxf(mx, pool_param[p]);
        float se = 0.f, e[PP];
        for (int p = 0; p < PP; p++) { e[p] = expf(pool_param[p]-mx); se += e[p]; }
        for (int p = 0; p < PP; p++) g_base_att[p] = e[p]/se;
    }
}

// ---------------- spatial mean -> noise; assemble time_emb ----------------
__global__ void k_noise(const float* __restrict__ x, const float* __restrict__ noise_w,
                        const float* __restrict__ noise_b)
{
    int bp = blockIdx.x;
    int t  = threadIdx.x;
    __shared__ float partial[256];
    __shared__ float mean[CC];
    const float* xb = x + (size_t)bp*NN*CC;
    float acc = 0.f;
    for (int i = t; i < NN*CC; i += 256) acc += xb[i];
    partial[t] = acc;
    __syncthreads();
    if (t < CC) {
        float s = 0.f;
        for (int j = t; j < 256; j += CC) s += partial[j];
        mean[t] = s*(1.f/(float)NN);
    }
    __syncthreads();
    if (t < 128) {
        float nz = noise_b[t];
        #pragma unroll
        for (int c = 0; c < CC; c++) nz += mean[c]*noise_w[c*128 + t];
        g_time_emb[bp*DD + 128 + t] = nz;
        g_time_emb[bp*DD + t]       = g_periodic[(bp % PP)*128 + t];
    }
}

__global__ void k_timevec(float* __restrict__ out)
{
    int b = blockIdx.x, e = threadIdx.x;
    float s = 0.f;
    for (int p = 0; p < PP; p++) s += g_time_emb[(b*PP + p)*DD + e];
    out[(size_t)BB*NN*DD + b*DD + e] = s*(1.f/24.f);
}

// ---------------- x DFT + attention-weighted x -----------------------------
// thread = (row r, channel c): xc_re/im over 13 freqs + xatt
__global__ void __launch_bounds__(256) k_xdft(const float* __restrict__ x)
{
    __shared__ float twc[KF*PP], tws[KF*PP], atts[PP];
    int tid = threadIdx.x;
    int r = blockIdx.x*16 + (tid >> 4);
    int c = tid & 15;
    int b = r >> 10, n = r & 1023;
    for (int i = tid; i < KF*PP; i += 256) { twc[i] = g_tw[i]; tws[i] = g_tw[KF*PP + i]; }
    if (tid < PP) atts[tid] = g_att[b*PP + tid];
    __syncthreads();
    float re[KF], im[KF], xa = 0.f;
    #pragma unroll
    for (int k = 0; k < KF; k++) { re[k] = 0.f; im[k] = 0.f; }
    #pragma unroll
    for (int p = 0; p < PP; p++) {
        float xv = x[((size_t)(b*PP + p)*NN + n)*CC + c];
        xa += atts[p]*xv;
        #pragma unroll
        for (int k = 0; k < KF; k++) {
            re[k] += twc[k*PP + p]*xv;
            im[k] -= tws[k*PP + p]*xv;
        }
    }
    g_xatt[(size_t)r*CC + c] = xa;
    #pragma unroll
    for (int k = 0; k < KF; k++) {
        g_xc[((size_t)k*RTOT + r)*32 + c]      = re[k];
        g_xc[((size_t)k*RTOT + r)*32 + 16 + c] = im[k];
    }
}

// ---------------- zpart = xatt @ W + te_att --------------------------------
__global__ void k_zpart(const float* __restrict__ w)
{
    int blk = blockIdx.x;          // 128 blocks x 64 rows
    int r0 = blk*64;
    int b = r0 >> 10;
    int t = threadIdx.x;
    __shared__ float Ws[CC*DD];
    __shared__ float xs[64*CC];
    __shared__ float tb[DD];
    for (int i = t; i < CC*DD; i += 256) Ws[i] = w[i];
    tb[t] = g_teatt[b*DD + t];
    for (int i = t; i < 64*CC; i += 256) xs[i] = g_xatt[(size_t)r0*CC + i];
    __syncthreads();
    float* zp = g_zpart + (size_t)r0*DD;
    for (int nn = 0; nn < 64; nn++) {
        float acc = tb[t];
        #pragma unroll
        for (int c = 0; c < CC; c++) acc += xs[nn*CC + c]*Ws[c*DD + t];
        zp[(size_t)nn*DD + t] = acc;
    }
}

// ---------------- gating: lagged diffs over raw x -------------------------
__device__ __forceinline__ float xr_val(const float* __restrict__ xb, int p, int i)
{
    float xp = xb[(size_t)p*16384 + i];
    float base;
    if (p <= 1) base = xb[i];
    else base = (xb[(size_t)(p-2)*16384 + i] + xb[(size_t)(p-1)*16384 + i] + xp)*(1.f/3.f);
    return xp - base;
}

__global__ void k_gd(const float* __restrict__ x)
{
    int bp = blockIdx.x;
    int b = bp / PP, p = bp % PP;
    int t = threadIdx.x;
    const float* xb = x + (size_t)b*PP*16384;
    float s0=0.f, s1=0.f, s2=0.f, s3=0.f;
    for (int i = t; i < 16384; i += 256) {
        float xr_p = xr_val(xb, p, i);
        if (p >= 1) s0 += fabsf(xr_p - xr_val(xb, p-1, i));
        if (p >= 2) s1 += fabsf(xr_p - xr_val(xb, p-2, i));
        if (p >= 4) s2 += fabsf(xr_p - xr_val(xb, p-4, i));
        if (p >= 6) s3 += fabsf(xr_p - xr_val(xb, p-6, i));
    }
    __shared__ float red[4][256];
    red[0][t]=s0; red[1][t]=s1; red[2][t]=s2; red[3][t]=s3;
    __syncthreads();
    if (t < 4) {
        float ss = 0.f;
        for (int j = 0; j < 256; j++) ss += red[t][j];
        g_dd[(b*4 + t)*PP + p] = ss*(1.f/16384.f);
    }
}

__global__ void k_att()
{
    __shared__ float sp[BB][4][PP];
    int t = threadIdx.x;
    if (t < 32) {
        int b = t >> 2, l = t & 3;
        float dv[PP], srt[PP];
        for (int p = 0; p < PP; p++) dv[p] = g_dd[(b*4 + l)*PP + p];
        for (int p = 0; p < PP; p++) srt[p] = dv[p];
        isort(srt, PP);
        float med = srt[11];
        for (int p = 0; p < PP; p++) srt[p] = fabsf(dv[p] - med);
        isort(srt, PP);
        float mad = srt[11];
        float denom = mad*1.4826f + 1e-6f;
        for (int p = 0; p < PP; p++) {
            float zz = (dv[p] - med)/denom;
            sp[b][l][p] = softplus_f(zz);
        }
    }
    __syncthreads();
    if (t < BB) {
        int b = t;
        float g[PP];
        for (int p = 0; p < PP; p++)
            g[p] = 0.25f*(sp[b][0][p] + sp[b][1][p] + sp[b][2][p] + sp[b][3][p]);
        float c = g[0];
        for (int p = 1; p < PP; p++) { c = 0.6f*c + 0.4f*g[p]; g[p] = c; }
        float gm = 0.f;
        for (int p = 0; p < PP; p++) gm += g[p];
        gm *= (1.f/24.f);
        float logit[PP], mx = -1e30f;
        for (int p = 0; p < PP; p++) {
            float gg = 1.f/(1.f + expf(-1.5f*(g[p] - gm)));
            logit[p] = g_base_att[p]*(1.f + gg);
            mx = fmaxf(mx, logit[p]);
        }
        float se = 0.f;
        for (int p = 0; p < PP; p++) { logit[p] = expf(logit[p] - mx); se += logit[p]; }
        for (int p = 0; p < PP; p++) g_att[b*PP + p] = logit[p]/se;
    }
}

// ---------------- launch ---------------------------------------------------
extern "C" void kernel_launch(void* const* d_in, const int* in_sizes, int n_in,
                              void* d_out, int out_size)
{
    const float* x         = (const float*)d_in[0];
    const float* in_proj_w = (const float*)d_in[1];
    const float* in_proj_b = (const float*)d_in[2];
    const float* pe_w1     = (const float*)d_in[3];
    const float* pe_b1     = (const float*)d_in[4];
    const float* pe_w2     = (const float*)d_in[5];
    const float* pe_b2     = (const float*)d_in[6];
    const float* noise_w   = (const float*)d_in[7];
    const float* noise_b   = (const float*)d_in[8];
    const float* sfe_w1    = (const float*)d_in[9];
    const float* sfe_b1    = (const float*)d_in[10];
    const float* sfe_w2    = (const float*)d_in[11];
    const float* sfe_b2    = (const float*)d_in[12];
    const float* comb_w1   = (const float*)d_in[13];
    const float* comb_b1   = (const float*)d_in[14];
    const float* comb_w2   = (const float*)d_in[15];
    const float* comb_b2   = (const float*)d_in[16];
    const float* pool_param= (const float*)d_in[17];
    float* out = (float*)d_out;

    float *p_xc, *p_p1, *p_hf1, *p_wp1T, *p_ckb;
    float *p_wc1T, *p_weffT, *p_wc2T, *p_zero;
    cudaGetSymbolAddress((void**)&p_xc,    g_xc);
    cudaGetSymbolAddress((void**)&p_p1,    g_p1);
    cudaGetSymbolAddress((void**)&p_hf1,   g_hf1);
    cudaGetSymbolAddress((void**)&p_wp1T,  g_wp1T);
    cudaGetSymbolAddress((void**)&p_ckb,   g_ckb);
    cudaGetSymbolAddress((void**)&p_wc1T,  g_wc1T);
    cudaGetSymbolAddress((void**)&p_weffT, g_weffT);
    cudaGetSymbolAddress((void**)&p_wc2T,  g_wc2T);
    cudaGetSymbolAddress((void**)&p_zero,  g_zero);

    const int SMEM = 16384*4;   // 64 KB dynamic
    cudaFuncSetAttribute(k_mma<0,0>, cudaFuncAttributeMaxDynamicSharedMemorySize, SMEM);
    cudaFuncSetAttribute(k_mma<1,0>, cudaFuncAttributeMaxDynamicSharedMemorySize, SMEM);
    cudaFuncSetAttribute(k_mma<0,1>, cudaFuncAttributeMaxDynamicSharedMemorySize, SMEM);
    cudaFuncSetAttribute(k_facc,     cudaFuncAttributeMaxDynamicSharedMemorySize, SMEM);

    // scalars / gating / embeddings
    k_init<<<1, 256>>>(pe_w1, pe_b1, pe_w2, pe_b2, pool_param);
    k_gd<<<BB*PP, 256>>>(x);
    k_att<<<1, 32>>>();
    k_noise<<<BB*PP, 256>>>(x, noise_w, noise_b);
    k_tedft<<<BB, 256>>>(in_proj_b, nullptr);
    k_timevec<<<BB, 256>>>(out);

    // x-side folds
    k_xdft<<<RTOT/16, 256>>>(x);
    k_zpart<<<RTOT/64, 256>>>(in_proj_w);

    // weight prep
    dim3 trb(32, 8);
    k_uv<<<KF, 256>>>(in_proj_w, sfe_w1);
    k_ckb<<<dim3(KF, BB), 256>>>(sfe_w1, sfe_b1);
    k_tr<<<dim3(256/32, 256/32, KF), trb>>>(comb_w1, p_wc1T, 256, 256);
    k_tr<<<dim3(256/32, 256/32, 1),  trb>>>(comb_w2, p_wc2T, 256, 256);
    k_mma<0,0><<<dim3(2, 2, KF), 256, SMEM>>>(p_wc1T, sfe_w2, p_zero, p_weffT,
        256, 256, 65536L, 65536L, 0L, 65536L, 0);
    k_bconst<<<1, 256>>>(comb_b1, sfe_b2, comb_w1);

    // p1_k = gelu(xc_k @ wp1T_k^T + c_kb)   (K=32)
    k_mma<1,0><<<dim3(2, 64, KF), 256, SMEM>>>(p_xc, p_wp1T, p_ckb, p_p1,
        32, 256, (long)RTOT*32, (long)DD*32, (long)BB*DD, (long)RTOT*256, DD);
    // hf1 = gelu(Σ_k p1_k @ WeffT_k + bconst)
    k_facc<<<dim3(2, 64), 256, SMEM>>>();
    // out = zpart + 0.3*(hf1 @ Wc2 + b2)
    k_mma<0,1><<<dim3(2, 64), 256, SMEM>>>(p_hf1, p_wc2T, comb_b2, out,
        256, 256, 0L, 0L, 0L, 0L, 0);
}

// round 13
// speedup vs baseline: 3.0071x; 1.1065x over previous
#include <cuda_runtime.h>
#include <cstdint>
#include <math.h>

#define BB 8
#define PP 24
#define CC 16
#define DD 256
#define NN 1024
#define KF 13
#define RTOT (BB*NN)      // 8192

// ---------------- scratch (device globals; no allocations) ----------------
__device__ __align__(128) float g_xc[(size_t)KF*RTOT*32];   // per-k [re(16)|im(16)]
__device__ __align__(128) float g_xatt[RTOT*CC];
__device__ __align__(128) float g_hf1[RTOT*DD];
__device__ __align__(128) float g_zpart[RTOT*DD];
__device__ __align__(128) float g_time_emb[BB*PP*DD];
__device__ __align__(128) float g_periodic[PP*128];
__device__ float g_base_att[PP];
__device__ float g_att[BB*PP];
__device__ float g_dd[BB*4*PP];
__device__ float g_tw[2*KF*PP];
__device__ float g_zero[DD];
__device__ float g_bconst[DD];
__device__ __align__(128) float g_tere[KF*BB*DD];
__device__ __align__(128) float g_teim[KF*BB*DD];
__device__ __align__(128) float g_teatt[BB*DD];
__device__ __align__(128) float g_ckb[KF*BB*DD];
// derived weights
__device__ __align__(128) float g_wp1T[KF*DD*32];     // [(k,o),32] = W@W1 fold, K-major
__device__ __align__(128) float g_wc1T[KF*DD*DD];
__device__ __align__(128) float g_weffT[KF*DD*DD];
__device__ __align__(128) float g_wc2T[DD*DD];

__device__ __forceinline__ float gelu_f(float v) {
    return 0.5f*v*(1.f + erff(v*0.70710678118654752f));
}
__device__ __forceinline__ float softplus_f(float v) {
    return fmaxf(v, 0.f) + log1pf(expf(-fabsf(v)));
}
__device__ void isort(float* a, int n) {
    for (int i = 1; i < n; i++) {
        float v = a[i]; int j = i-1;
        while (j >= 0 && a[j] > v) { a[j+1] = a[j]; j--; }
        a[j+1] = v;
    }
}
__device__ __forceinline__ float tf32r(float x) {
    uint32_t r;
    asm("cvt.rna.tf32.f32 %0, %1;" : "=r"(r) : "f"(x));
    return __uint_as_float(r);
}

// ---------------- warp mma m16n8k8 tf32 ------------------------------------
__device__ __forceinline__ void mma_tf32(float* d, const float4& a, const float2& b) {
    asm volatile("mma.sync.aligned.m16n8k8.row.col.f32.tf32.tf32.f32 "
        "{%0,%1,%2,%3}, {%4,%5,%6,%7}, {%8,%9}, {%0,%1,%2,%3};"
        : "+f"(d[0]), "+f"(d[1]), "+f"(d[2]), "+f"(d[3])
        : "r"(__float_as_uint(a.x)), "r"(__float_as_uint(a.y)),
          "r"(__float_as_uint(a.z)), "r"(__float_as_uint(a.w)),
          "r"(__float_as_uint(b.x)), "r"(__float_as_uint(b.y)));
}

// GEMM building blocks (CTA tile 128x128, 8 warps, K-chunk 32)
__device__ __forceinline__ void gload(const float* A, const float* Wt, int bm, int bn,
                                      int K, int koff, int tid, float4* ra, float4* rb)
{
    #pragma unroll
    for (int q = 0; q < 4; q++) {
        int f = tid + q*256;
        int row = f >> 3, seg = f & 7;
        ra[q] = *(const float4*)(A  + (size_t)(bm + row)*K + koff + seg*4);
        rb[q] = *(const float4*)(Wt + (size_t)(bn + row)*K + koff + seg*4);
    }
}
__device__ __forceinline__ void gscatter(const float4* ra, const float4* rb,
                                         float* sa, float* sb, int tid)
{
    #pragma unroll
    for (int q = 0; q < 4; q++) {
        int f = tid + q*256;
        int row = f >> 3, seg = f & 7;
        int ks = seg >> 1, posK = seg & 1;
        int mt = row >> 4, posM = (row >> 3) & 1, gga = row & 7;
        int abase = ((mt*4 + ks)*32 + gga*4)*4 + posK*2 + posM;
        float av[4] = {ra[q].x, ra[q].y, ra[q].z, ra[q].w};
        #pragma unroll
        for (int e = 0; e < 4; e++) sa[abase + e*4] = tf32r(av[e]);
        int nt = row >> 3, ggb = row & 7;
        int bbase = ((nt*4 + ks)*32 + ggb*4)*2 + posK;
        float bv[4] = {rb[q].x, rb[q].y, rb[q].z, rb[q].w};
        #pragma unroll
        for (int e = 0; e < 4; e++) sb[bbase + e*2] = tf32r(bv[e]);
    }
}
// scatter one B tile (128 rows x 32 cols) from src (ld = K, row offset rbase)
__device__ __forceinline__ void bscatter(const float* src, int ld, int rbase, int coff,
                                         float* sb, int tid)
{
    #pragma unroll
    for (int q = 0; q < 4; q++) {
        int f = tid + q*256;
        int row = f >> 3, seg = f & 7;
        float4 v = *(const float4*)(src + (size_t)(rbase + row)*ld + coff + seg*4);
        int ks = seg >> 1, posK = seg & 1;
        int bbase = (((row >> 3)*4 + ks)*32 + (row & 7)*4)*2 + posK;
        float bv[4] = {v.x, v.y, v.z, v.w};
        #pragma unroll
        for (int e = 0; e < 4; e++) sb[bbase + e*2] = tf32r(bv[e]);
    }
}
__device__ __forceinline__ void gmma(const float* sa, const float* sb,
                                     int wid, int lane, float acc[2][8][4])
{
    #pragma unroll
    for (int ks = 0; ks < 4; ks++) {
        float4 af[2];
        #pragma unroll
        for (int i = 0; i < 2; i++) {
            int mt = (wid & 3)*2 + i;
            af[i] = *(const float4*)&sa[((mt*4 + ks)*32 + lane)*4];
        }
        float2 bf[8];
        #pragma unroll
        for (int j = 0; j < 8; j++) {
            int nt = (wid >> 2)*8 + j;
            bf[j] = *(const float2*)&sb[((nt*4 + ks)*32 + lane)*2];
        }
        #pragma unroll
        for (int i = 0; i < 2; i++)
            #pragma unroll
            for (int j = 0; j < 8; j++)
                mma_tf32(acc[i][j], af[i], bf[j]);
    }
}

// ---------------- generic GEMM: C = act(A @ Wt^T + bias) -------------------
template<int ACT, int FIN>
__global__ void __launch_bounds__(256) k_mma(
    const float* __restrict__ A, const float* __restrict__ Wt,
    const float* __restrict__ bias, float* __restrict__ C,
    int K, int ldc, long sA, long sW, long sB, long sC, int bstride)
{
    extern __shared__ float smem[];
    float* sa0 = smem;         float* sa1 = smem + 4096;
    float* sb0 = smem + 8192;  float* sb1 = smem + 12288;
    int z = blockIdx.z;
    int bm = blockIdx.y*128, bn = blockIdx.x*128;
    A    += (size_t)z*sA;
    Wt   += (size_t)z*sW;
    bias += (size_t)z*sB + (size_t)(bm >> 10)*bstride;
    C    += (size_t)z*sC;
    int tid = threadIdx.x, wid = tid >> 5, lane = tid & 31;
    int g = lane >> 2, tig = lane & 3;
    int wm = (wid & 3)*32, wn = (wid >> 2)*64;

    float acc[2][8][4];
    #pragma unroll
    for (int i = 0; i < 2; i++)
        #pragma unroll
        for (int j = 0; j < 8; j++)
            #pragma unroll
            for (int q = 0; q < 4; q++) acc[i][j][q] = 0.f;

    int nch = K >> 5;
    float4 ra[4], rb[4];
    gload(A, Wt, bm, bn, K, 0, tid, ra, rb);
    gscatter(ra, rb, sa0, sb0, tid);
    __syncthreads();
    for (int c = 0; c < nch; c++) {
        int buf = c & 1;
        if (c + 1 < nch) gload(A, Wt, bm, bn, K, (c+1)*32, tid, ra, rb);
        gmma(buf ? sa1 : sa0, buf ? sb1 : sb0, wid, lane, acc);
        if (c + 1 < nch) gscatter(ra, rb, buf ? sa0 : sa1, buf ? sb0 : sb1, tid);
        __syncthreads();
    }

    #pragma unroll
    for (int i = 0; i < 2; i++) {
        int r0 = bm + wm + i*16 + g;
        #pragma unroll
        for (int j = 0; j < 8; j++) {
            int col = bn + wn + j*8 + tig*2;
            float b0 = bias[col], b1 = bias[col+1];
            float v0 = acc[i][j][0] + b0, v1 = acc[i][j][1] + b1;
            float v2 = acc[i][j][2] + b0, v3 = acc[i][j][3] + b1;
            if (ACT) { v0 = gelu_f(v0); v1 = gelu_f(v1); v2 = gelu_f(v2); v3 = gelu_f(v3); }
            if (FIN) {
                v0 = g_zpart[(size_t)r0*ldc + col]       + 0.3f*v0;
                v1 = g_zpart[(size_t)r0*ldc + col + 1]   + 0.3f*v1;
                v2 = g_zpart[(size_t)(r0+8)*ldc + col]   + 0.3f*v2;
                v3 = g_zpart[(size_t)(r0+8)*ldc + col+1] + 0.3f*v3;
            }
            *(float2*)(C + (size_t)r0*ldc + col)     = make_float2(v0, v1);
            *(float2*)(C + (size_t)(r0+8)*ldc + col) = make_float2(v2, v3);
        }
    }
}

// ---------------- fully fused: hf1 = gelu(Σ_k gelu(xc_k@wp1T_k^T + ckb)@weffT_k + bconst)
// p1 tiles regenerated in SMEM, never hitting DRAM.
__global__ void __launch_bounds__(256) k_ff()
{
    extern __shared__ float smem[];
    float* saA = smem;             // 4 chunks x 4096 (A-fragments of p1 half)
    float* sxc = smem + 16384;     // 4096 (xc A-chunk)
    float* swp = smem + 20480;     // 2 x 4096 (wp1T B halves)
    float* swf = smem + 28672;     // 2 x 4096 (weff B chunks, dbl buf)
    int bm = blockIdx.y*128, bn = blockIdx.x*128;
    int b  = bm >> 10;
    int tid = threadIdx.x, wid = tid >> 5, lane = tid & 31;
    int g = lane >> 2, tig = lane & 3;
    int wm = (wid & 3)*32, wn = (wid >> 2)*64;

    float ACC[2][8][4];
    #pragma unroll
    for (int i = 0; i < 2; i++)
        #pragma unroll
        for (int j = 0; j < 8; j++)
            #pragma unroll
            for (int q = 0; q < 4; q++) ACC[i][j][q] = 0.f;

    for (int k = 0; k < KF; k++) {
        // xc A-chunk (K=32, one chunk)
        {
            const float* Axc = g_xc + ((size_t)k*RTOT + bm)*32;
            #pragma unroll
            for (int q = 0; q < 4; q++) {
                int f = tid + q*256;
                int row = f >> 3, seg = f & 7;
                float4 v = *(const float4*)(Axc + (size_t)row*32 + seg*4);
                int ks = seg >> 1, posK = seg & 1;
                int abase = (((row >> 4)*4 + ks)*32 + (row & 7)*4)*4 + posK*2 + ((row >> 3) & 1);
                float av[4] = {v.x, v.y, v.z, v.w};
                #pragma unroll
                for (int e = 0; e < 4; e++) sxc[abase + e*4] = tf32r(av[e]);
            }
            // wp1T B: both 128-row halves
            const float* Bwp = g_wp1T + (size_t)k*DD*32;
            bscatter(Bwp, 32, 0,   0, swp,        tid);
            bscatter(Bwp, 32, 128, 0, swp + 4096, tid);
        }
        __syncthreads();
        #pragma unroll
        for (int h = 0; h < 2; h++) {
            // GEMM1: p1 half = xc @ wp1T_h
            float a1[2][8][4];
            #pragma unroll
            for (int i = 0; i < 2; i++)
                #pragma unroll
                for (int j = 0; j < 8; j++)
                    #pragma unroll
                    for (int q = 0; q < 4; q++) a1[i][j][q] = 0.f;
            gmma(sxc, swp + h*4096, wid, lane, a1);
            __syncthreads();   // all prior readers of saA done
            // bias + gelu + scatter into A-fragment layout
            const float* ck = g_ckb + (size_t)(k*BB + b)*DD + h*128;
            #pragma unroll
            for (int i = 0; i < 2; i++)
                #pragma unroll
                for (int j = 0; j < 8; j++)
                    #pragma unroll
                    for (int q = 0; q < 4; q++) {
                        int row  = wm + i*16 + g + ((q >> 1) ? 8 : 0);
                        int kcol = wn + j*8 + tig*2 + (q & 1);
                        float val = gelu_f(a1[i][j][q] + ck[kcol]);
                        int cc = kcol >> 5, kk = kcol & 31;
                        int idx = cc*4096
                                + (((row >> 4)*4 + (kk >> 3))*32 + (row & 7)*4 + (kk & 3))*4
                                + ((kk >> 2) & 1)*2 + ((row >> 3) & 1);
                        saA[idx] = tf32r(val);
                    }
            __syncthreads();
            // GEMM2: 4 chunks vs weffT
            const float* Wf = g_weffT + (size_t)k*65536;
            #pragma unroll
            for (int cc = 0; cc < 4; cc++) {
                float* sbuf = swf + (cc & 1)*4096;
                bscatter(Wf, 256, bn, h*128 + cc*32, sbuf, tid);
                __syncthreads();
                gmma(saA + cc*4096, sbuf, wid, lane, ACC);
            }
            __syncthreads();
        }
    }

    // epilogue
    #pragma unroll
    for (int i = 0; i < 2; i++) {
        int r0 = bm + wm + i*16 + g;
        #pragma unroll
        for (int j = 0; j < 8; j++) {
            int col = bn + wn + j*8 + tig*2;
            float b0 = g_bconst[col], b1 = g_bconst[col+1];
            float2 lo = make_float2(gelu_f(ACC[i][j][0] + b0), gelu_f(ACC[i][j][1] + b1));
            float2 hi = make_float2(gelu_f(ACC[i][j][2] + b0), gelu_f(ACC[i][j][3] + b1));
            *(float2*)(g_hf1 + (size_t)r0*256 + col)     = lo;
            *(float2*)(g_hf1 + (size_t)(r0+8)*256 + col) = hi;
        }
    }
}

// ---------------- weight transpose [K,N] -> [N,K] --------------------------
__global__ void k_tr(const float* __restrict__ W, float* __restrict__ WT, int K, int N)
{
    __shared__ float tile[32][33];
    int z = blockIdx.z;
    W  += (size_t)z*K*N;
    WT += (size_t)z*K*N;
    int k0 = blockIdx.y*32, n0 = blockIdx.x*32;
    int tx = threadIdx.x, ty = threadIdx.y;
    for (int i = ty; i < 32; i += 8) tile[i][tx] = W[(size_t)(k0+i)*N + n0+tx];
    __syncthreads();
    for (int i = ty; i < 32; i += 8) WT[(size_t)(n0+i)*K + k0+tx] = tile[tx][i];
}

// ---------------- folded weights: wp1T[k][o][c<16]=Σ_e W[c][e]W1_k[e][o] ----
__global__ void k_uv(const float* __restrict__ W, const float* __restrict__ W1)
{
    int k = blockIdx.x, o = threadIdx.x;
    __shared__ float Ws[CC*DD];
    for (int i = o; i < CC*DD; i += 256) Ws[i] = W[i];
    __syncthreads();
    float acc[32];
    #pragma unroll
    for (int c = 0; c < 32; c++) acc[c] = 0.f;
    const float* w1 = W1 + (size_t)k*512*DD;
    for (int e = 0; e < 256; e++) {
        float u = w1[(size_t)e*DD + o];
        float v = w1[(size_t)(256+e)*DD + o];
        #pragma unroll
        for (int c = 0; c < 16; c++) {
            acc[c]      += Ws[c*DD + e]*u;
            acc[16 + c] += Ws[c*DD + e]*v;
        }
    }
    float* dst = g_wp1T + ((size_t)k*DD + o)*32;
    #pragma unroll
    for (int c = 0; c < 32; c++) dst[c] = acc[c];
}

// ---------------- te DFT + te_att ------------------------------------------
__global__ void k_tedft(const float* __restrict__ in_proj_b)
{
    int b = blockIdx.x, e = threadIdx.x;
    float teb[PP];
    #pragma unroll
    for (int p = 0; p < PP; p++)
        teb[p] = g_time_emb[(b*PP + p)*DD + e] + in_proj_b[e];
    float ta = 0.f;
    #pragma unroll
    for (int p = 0; p < PP; p++) ta += g_att[b*PP + p]*teb[p];
    g_teatt[b*DD + e] = ta;
    for (int k = 0; k < KF; k++) {
        float re = 0.f, im = 0.f;
        #pragma unroll
        for (int p = 0; p < PP; p++) {
            re += teb[p]*g_tw[k*PP + p];
            im -= teb[p]*g_tw[KF*PP + k*PP + p];
        }
        g_tere[(k*BB + b)*DD + e] = re;
        g_teim[(k*BB + b)*DD + e] = im;
    }
}

// ---------------- c_kb[o] = b1_k[o] + Σ_e tere*W1_k[e][o] + teim*W1_k[256+e][o]
__global__ void k_ckb(const float* __restrict__ W1, const float* __restrict__ b1)
{
    int k = blockIdx.x, b = blockIdx.y, o = threadIdx.x;
    __shared__ float sre[DD], sim[DD];
    sre[o] = g_tere[(k*BB + b)*DD + o];
    sim[o] = g_teim[(k*BB + b)*DD + o];
    __syncthreads();
    float acc = b1[(size_t)k*DD + o];
    const float* w1 = W1 + (size_t)k*512*DD;
    for (int e = 0; e < 256; e++)
        acc += sre[e]*w1[(size_t)e*DD + o] + sim[e]*w1[(size_t)(256+e)*DD + o];
    g_ckb[(k*BB + b)*DD + o] = acc;
}

// ---------------- folded bias: bconst = comb_b1 + Σ b2·Wc1 -----------------
__global__ void k_bconst(const float* __restrict__ comb_b1,
                         const float* __restrict__ sfe_b2,
                         const float* __restrict__ comb_w1)
{
    int j = threadIdx.x;
    float s = comb_b1[j];
    for (int i = 0; i < KF*256; i++) s += sfe_b2[i]*comb_w1[(size_t)i*256 + j];
    g_bconst[j] = s;
}

// ---------------- tiny init ------------------------------------------------
__global__ void k_init(const float* __restrict__ pe_w1, const float* __restrict__ pe_b1,
                       const float* __restrict__ pe_w2, const float* __restrict__ pe_b2,
                       const float* __restrict__ pool_param)
{
    int t = threadIdx.x;
    for (int idx = t; idx < KF*PP; idx += blockDim.x) {
        int k = idx / PP, p = idx % PP;
        double ang = 2.0*M_PI*(double)(k*p)/24.0;
        g_tw[idx]        = (float)cos(ang);
        g_tw[KF*PP+idx]  = (float)sin(ang);
    }
    if (t < 2*PP) {
        int kk = t / PP, p = t % PP;
        double period = (kk == 0) ? 24.0 : 72.0;
        double ph = 2.0*M_PI*(double)p/period;
        float s = (float)sin(ph), c = (float)cos(ph);
        float hid[64];
        #pragma unroll
        for (int o = 0; o < 64; o++) {
            float v = s*pe_w1[kk*128 + o] + c*pe_w1[kk*128 + 64 + o] + pe_b1[kk*64 + o];
            hid[o] = gelu_f(v);
        }
        for (int q = 0; q < 64; q++) {
            float acc = pe_b2[kk*64 + q];
            #pragma unroll
            for (int o = 0; o < 64; o++) acc += hid[o]*pe_w2[kk*4096 + o*64 + q];
            g_periodic[p*128 + kk*64 + q] = acc;
        }
    }
    if (t == 0) {
        float mx = -1e30f;
        for (int p = 0; p < PP; p++) mx = fmaxf(mx, pool_param[p]);
        float se = 0.f, e[PP];
        for (int p = 0; p < PP; p++) { e[p] = expf(pool_param[p]-mx); se += e[p]; }
        for (int p = 0; p < PP; p++) g_base_att[p] = e[p]/se;
    }
}

// ---------------- spatial mean -> noise; assemble time_emb ----------------
__global__ void k_noise(const float* __restrict__ x, const float* __restrict__ noise_w,
                        const float* __restrict__ noise_b)
{
    int bp = blockIdx.x;
    int t  = threadIdx.x;
    __shared__ float partial[256];
    __shared__ float mean[CC];
    const float* xb = x + (size_t)bp*NN*CC;
    float acc = 0.f;
    for (int i = t; i < NN*CC; i += 256) acc += xb[i];
    partial[t] = acc;
    __syncthreads();
    if (t < CC) {
        float s = 0.f;
        for (int j = t; j < 256; j += CC) s += partial[j];
        mean[t] = s*(1.f/(float)NN);
    }
    __syncthreads();
    if (t < 128) {
        float nz = noise_b[t];
        #pragma unroll
        for (int c = 0; c < CC; c++) nz += mean[c]*noise_w[c*128 + t];
        g_time_emb[bp*DD + 128 + t] = nz;
        g_time_emb[bp*DD + t]       = g_periodic[(bp % PP)*128 + t];
    }
}

__global__ void k_timevec(float* __restrict__ out)
{
    int b = blockIdx.x, e = threadIdx.x;
    float s = 0.f;
    for (int p = 0; p < PP; p++) s += g_time_emb[(b*PP + p)*DD + e];
    out[(size_t)BB*NN*DD + b*DD + e] = s*(1.f/24.f);
}

// ---------------- x DFT + attention-weighted x -----------------------------
__global__ void __launch_bounds__(256) k_xdft(const float* __restrict__ x)
{
    __shared__ float twc[KF*PP], tws[KF*PP], atts[PP];
    int tid = threadIdx.x;
    int r = blockIdx.x*16 + (tid >> 4);
    int c = tid & 15;
    int b = r >> 10, n = r & 1023;
    for (int i = tid; i < KF*PP; i += 256) { twc[i] = g_tw[i]; tws[i] = g_tw[KF*PP + i]; }
    if (tid < PP) atts[tid] = g_att[b*PP + tid];
    __syncthreads();
    float re[KF], im[KF], xa = 0.f;
    #pragma unroll
    for (int k = 0; k < KF; k++) { re[k] = 0.f; im[k] = 0.f; }
    #pragma unroll
    for (int p = 0; p < PP; p++) {
        float xv = x[((size_t)(b*PP + p)*NN + n)*CC + c];
        xa += atts[p]*xv;
        #pragma unroll
        for (int k = 0; k < KF; k++) {
            re[k] += twc[k*PP + p]*xv;
            im[k] -= tws[k*PP + p]*xv;
        }
    }
    g_xatt[(size_t)r*CC + c] = xa;
    #pragma unroll
    for (int k = 0; k < KF; k++) {
        g_xc[((size_t)k*RTOT + r)*32 + c]      = re[k];
        g_xc[((size_t)k*RTOT + r)*32 + 16 + c] = im[k];
    }
}

// ---------------- zpart = xatt @ W + te_att --------------------------------
__global__ void k_zpart(const float* __restrict__ w)
{
    int blk = blockIdx.x;
    int r0 = blk*64;
    int b = r0 >> 10;
    int t = threadIdx.x;
    __shared__ float Ws[CC*DD];
    __shared__ float xs[64*CC];
    __shared__ float tb[DD];
    for (int i = t; i < CC*DD; i += 256) Ws[i] = w[i];
    tb[t] = g_teatt[b*DD + t];
    for (int i = t; i < 64*CC; i += 256) xs[i] = g_xatt[(size_t)r0*CC + i];
    __syncthreads();
    float* zp = g_zpart + (size_t)r0*DD;
    for (int nn = 0; nn < 64; nn++) {
        float acc = tb[t];
        #pragma unroll
        for (int c = 0; c < CC; c++) acc += xs[nn*CC + c]*Ws[c*DD + t];
        zp[(size_t)nn*DD + t] = acc;
    }
}

// ---------------- gating: lagged diffs over raw x -------------------------
__device__ __forceinline__ float xr_val(const float* __restrict__ xb, int p, int i)
{
    float xp = xb[(size_t)p*16384 + i];
    float base;
    if (p <= 1) base = xb[i];
    else base = (xb[(size_t)(p-2)*16384 + i] + xb[(size_t)(p-1)*16384 + i] + xp)*(1.f/3.f);
    return xp - base;
}

__global__ void k_gd(const float* __restrict__ x)
{
    int bp = blockIdx.x;
    int b = bp / PP, p = bp % PP;
    int t = threadIdx.x;
    const float* xb = x + (size_t)b*PP*16384;
    float s0=0.f, s1=0.f, s2=0.f, s3=0.f;
    for (int i = t; i < 16384; i += 256) {
        float xr_p = xr_val(xb, p, i);
        if (p >= 1) s0 += fabsf(xr_p - xr_val(xb, p-1, i));
        if (p >= 2) s1 += fabsf(xr_p - xr_val(xb, p-2, i));
        if (p >= 4) s2 += fabsf(xr_p - xr_val(xb, p-4, i));
        if (p >= 6) s3 += fabsf(xr_p - xr_val(xb, p-6, i));
    }
    __shared__ float red[4][256];
    red[0][t]=s0; red[1][t]=s1; red[2][t]=s2; red[3][t]=s3;
    __syncthreads();
    if (t < 4) {
        float ss = 0.f;
        for (int j = 0; j < 256; j++) ss += red[t][j];
        g_dd[(b*4 + t)*PP + p] = ss*(1.f/16384.f);
    }
}

__global__ void k_att()
{
    __shared__ float sp[BB][4][PP];
    int t = threadIdx.x;
    if (t < 32) {
        int b = t >> 2, l = t & 3;
        float dv[PP], srt[PP];
        for (int p = 0; p < PP; p++) dv[p] = g_dd[(b*4 + l)*PP + p];
        for (int p = 0; p < PP; p++) srt[p] = dv[p];
        isort(srt, PP);
        float med = srt[11];
        for (int p = 0; p < PP; p++) srt[p] = fabsf(dv[p] - med);
        isort(srt, PP);
        float mad = srt[11];
        float denom = mad*1.4826f + 1e-6f;
        for (int p = 0; p < PP; p++) {
            float zz = (dv[p] - med)/denom;
            sp[b][l][p] = softplus_f(zz);
        }
    }
    __syncthreads();
    if (t < BB) {
        int b = t;
        float g[PP];
        for (int p = 0; p < PP; p++)
            g[p] = 0.25f*(sp[b][0][p] + sp[b][1][p] + sp[b][2][p] + sp[b][3][p]);
        float c = g[0];
        for (int p = 1; p < PP; p++) { c = 0.6f*c + 0.4f*g[p]; g[p] = c; }
        float gm = 0.f;
        for (int p = 0; p < PP; p++) gm += g[p];
        gm *= (1.f/24.f);
        float logit[PP], mx = -1e30f;
        for (int p = 0; p < PP; p++) {
            float gg = 1.f/(1.f + expf(-1.5f*(g[p] - gm)));
            logit[p] = g_base_att[p]*(1.f + gg);
            mx = fmaxf(mx, logit[p]);
        }
        float se = 0.f;
        for (int p = 0; p < PP; p++) { logit[p] = expf(logit[p] - mx); se += logit[p]; }
        for (int p = 0; p < PP; p++) g_att[b*PP + p] = logit[p]/se;
    }
}

// ---------------- launch ---------------------------------------------------
extern "C" void kernel_launch(void* const* d_in, const int* in_sizes, int n_in,
                              void* d_out, int out_size)
{
    const float* x         = (const float*)d_in[0];
    const float* in_proj_w = (const float*)d_in[1];
    const float* in_proj_b = (const float*)d_in[2];
    const float* pe_w1     = (const float*)d_in[3];
    const float* pe_b1     = (const float*)d_in[4];
    const float* pe_w2     = (const float*)d_in[5];
    const float* pe_b2     = (const float*)d_in[6];
    const float* noise_w   = (const float*)d_in[7];
    const float* noise_b   = (const float*)d_in[8];
    const float* sfe_w1    = (const float*)d_in[9];
    const float* sfe_b1    = (const float*)d_in[10];
    const float* sfe_w2    = (const float*)d_in[11];
    const float* sfe_b2    = (const float*)d_in[12];
    const float* comb_w1   = (const float*)d_in[13];
    const float* comb_b1   = (const float*)d_in[14];
    const float* comb_w2   = (const float*)d_in[15];
    const float* comb_b2   = (const float*)d_in[16];
    const float* pool_param= (const float*)d_in[17];
    float* out = (float*)d_out;

    float *p_hf1, *p_wc1T, *p_weffT, *p_wc2T, *p_zero;
    cudaGetSymbolAddress((void**)&p_hf1,   g_hf1);
    cudaGetSymbolAddress((void**)&p_wc1T,  g_wc1T);
    cudaGetSymbolAddress((void**)&p_weffT, g_weffT);
    cudaGetSymbolAddress((void**)&p_wc2T,  g_wc2T);
    cudaGetSymbolAddress((void**)&p_zero,  g_zero);

    const int SMEM  = 16384*4;     // 64 KB for k_mma
    const int SMEMF = 36864*4;     // 144 KB for k_ff
    cudaFuncSetAttribute(k_mma<0,0>, cudaFuncAttributeMaxDynamicSharedMemorySize, SMEM);
    cudaFuncSetAttribute(k_mma<0,1>, cudaFuncAttributeMaxDynamicSharedMemorySize, SMEM);
    cudaFuncSetAttribute(k_ff,       cudaFuncAttributeMaxDynamicSharedMemorySize, SMEMF);

    // scalars / gating / embeddings
    k_init<<<1, 256>>>(pe_w1, pe_b1, pe_w2, pe_b2, pool_param);
    k_gd<<<BB*PP, 256>>>(x);
    k_att<<<1, 32>>>();
    k_noise<<<BB*PP, 256>>>(x, noise_w, noise_b);
    k_tedft<<<BB, 256>>>(in_proj_b);
    k_timevec<<<BB, 256>>>(out);

    // x-side folds
    k_xdft<<<RTOT/16, 256>>>(x);
    k_zpart<<<RTOT/64, 256>>>(in_proj_w);

    // weight prep
    dim3 trb(32, 8);
    k_uv<<<KF, 256>>>(in_proj_w, sfe_w1);
    k_ckb<<<dim3(KF, BB), 256>>>(sfe_w1, sfe_b1);
    k_tr<<<dim3(256/32, 256/32, KF), trb>>>(comb_w1, p_wc1T, 256, 256);
    k_tr<<<dim3(256/32, 256/32, 1),  trb>>>(comb_w2, p_wc2T, 256, 256);
    k_mma<0,0><<<dim3(2, 2, KF), 256, SMEM>>>(p_wc1T, sfe_w2, p_zero, p_weffT,
        256, 256, 65536L, 65536L, 0L, 65536L, 0);
    k_bconst<<<1, 256>>>(comb_b1, sfe_b2, comb_w1);

    // fused sfe1 + sfe2·comb1: hf1
    k_ff<<<dim3(2, 64), 256, SMEMF>>>();
    // out = zpart + 0.3*(hf1 @ Wc2 + b2)
    k_mma<0,1><<<dim3(2, 64), 256, SMEM>>>(p_hf1, p_wc2T, comb_b2, out,
        256, 256, 0L, 0L, 0L, 0L, 0);
}

// round 14
// speedup vs baseline: 3.3429x; 1.1117x over previous
#include <cuda_runtime.h>
#include <cstdint>
#include <math.h>

#define BB 8
#define PP 24
#define CC 16
#define DD 256
#define NN 1024
#define KF 13
#define RTOT (BB*NN)      // 8192

// ---------------- scratch (device globals; no allocations) ----------------
__device__ __align__(128) float g_xc[(size_t)KF*RTOT*32];   // per-k [re(16)|im(16)]
__device__ __align__(128) float g_xatt[RTOT*CC];
__device__ __align__(128) float g_hf1[RTOT*DD];
__device__ __align__(128) float g_zpart[RTOT*DD];
__device__ __align__(128) float g_time_emb[BB*PP*DD];
__device__ __align__(128) float g_periodic[PP*128];
__device__ float g_base_att[PP];
__device__ float g_att[BB*PP];
__device__ float g_dd[BB*4*PP];
__device__ float g_tw[2*KF*PP];
__device__ float g_zero[DD];
__device__ float g_bconst[DD];
__device__ float g_bcp[KF*DD];
__device__ __align__(128) float g_tere[KF*BB*DD];
__device__ __align__(128) float g_teim[KF*BB*DD];
__device__ __align__(128) float g_teatt[BB*DD];
__device__ __align__(128) float g_ckb[KF*BB*DD];
// derived weights
__device__ __align__(128) float g_wp1T[KF*DD*32];      // [(k,o),32] = W@W1 fold, K-major
__device__ __align__(128) float g_uvp[KF*4*DD*32];     // k_uv partials
__device__ __align__(128) float g_wc1T[KF*DD*DD];
__device__ __align__(128) float g_weffT[KF*DD*DD];
__device__ __align__(128) float g_wc2T[DD*DD];
// fragment-permuted, tf32-rounded copies for k_ff
__device__ __align__(128) float g_weffP[(size_t)KF*2*8*4096];
__device__ __align__(128) float g_wp1P[KF*2*4096];

__device__ __forceinline__ float gelu_f(float v) {
    return 0.5f*v*(1.f + erff(v*0.70710678118654752f));
}
__device__ __forceinline__ float softplus_f(float v) {
    return fmaxf(v, 0.f) + log1pf(expf(-fabsf(v)));
}
__device__ void isort(float* a, int n) {
    for (int i = 1; i < n; i++) {
        float v = a[i]; int j = i-1;
        while (j >= 0 && a[j] > v) { a[j+1] = a[j]; j--; }
        a[j+1] = v;
    }
}
__device__ __forceinline__ float tf32r(float x) {
    uint32_t r;
    asm("cvt.rna.tf32.f32 %0, %1;" : "=r"(r) : "f"(x));
    return __uint_as_float(r);
}
__device__ __forceinline__ uint32_t smem_u32(const void* p) {
    uint32_t a;
    asm("{ .reg .u64 t; cvta.to.shared.u64 t, %1; cvt.u32.u64 %0, t; }" : "=r"(a) : "l"(p));
    return a;
}
#define CP_ASYNC16(smaddr, gptr) \
    asm volatile("cp.async.ca.shared.global [%0], [%1], 16;" :: "r"(smaddr), "l"(gptr))
#define CP_COMMIT() asm volatile("cp.async.commit_group;" ::: "memory")
#define CP_WAIT0()  asm volatile("cp.async.wait_group 0;" ::: "memory")

// ---------------- warp mma m16n8k8 tf32 ------------------------------------
__device__ __forceinline__ void mma_tf32(float* d, const float4& a, const float2& b) {
    asm volatile("mma.sync.aligned.m16n8k8.row.col.f32.tf32.tf32.f32 "
        "{%0,%1,%2,%3}, {%4,%5,%6,%7}, {%8,%9}, {%0,%1,%2,%3};"
        : "+f"(d[0]), "+f"(d[1]), "+f"(d[2]), "+f"(d[3])
        : "r"(__float_as_uint(a.x)), "r"(__float_as_uint(a.y)),
          "r"(__float_as_uint(a.z)), "r"(__float_as_uint(a.w)),
          "r"(__float_as_uint(b.x)), "r"(__float_as_uint(b.y)));
}

// GEMM building blocks (CTA tile 128x128, 8 warps, K-chunk 32)
__device__ __forceinline__ void gload(const float* A, const float* Wt, int bm, int bn,
                                      int K, int koff, int tid, float4* ra, float4* rb)
{
    #pragma unroll
    for (int q = 0; q < 4; q++) {
        int f = tid + q*256;
        int row = f >> 3, seg = f & 7;
        ra[q] = *(const float4*)(A  + (size_t)(bm + row)*K + koff + seg*4);
        rb[q] = *(const float4*)(Wt + (size_t)(bn + row)*K + koff + seg*4);
    }
}
__device__ __forceinline__ void gscatter(const float4* ra, const float4* rb,
                                         float* sa, float* sb, int tid)
{
    #pragma unroll
    for (int q = 0; q < 4; q++) {
        int f = tid + q*256;
        int row = f >> 3, seg = f & 7;
        int ks = seg >> 1, posK = seg & 1;
        int mt = row >> 4, posM = (row >> 3) & 1, gga = row & 7;
        int abase = ((mt*4 + ks)*32 + gga*4)*4 + posK*2 + posM;
        float av[4] = {ra[q].x, ra[q].y, ra[q].z, ra[q].w};
        #pragma unroll
        for (int e = 0; e < 4; e++) sa[abase + e*4] = tf32r(av[e]);
        int nt = row >> 3, ggb = row & 7;
        int bbase = ((nt*4 + ks)*32 + ggb*4)*2 + posK;
        float bv[4] = {rb[q].x, rb[q].y, rb[q].z, rb[q].w};
        #pragma unroll
        for (int e = 0; e < 4; e++) sb[bbase + e*2] = tf32r(bv[e]);
    }
}
__device__ __forceinline__ void gmma(const float* sa, const float* sb,
                                     int wid, int lane, float acc[2][8][4])
{
    #pragma unroll
    for (int ks = 0; ks < 4; ks++) {
        float4 af[2];
        #pragma unroll
        for (int i = 0; i < 2; i++) {
            int mt = (wid & 3)*2 + i;
            af[i] = *(const float4*)&sa[((mt*4 + ks)*32 + lane)*4];
        }
        float2 bf[8];
        #pragma unroll
        for (int j = 0; j < 8; j++) {
            int nt = (wid >> 2)*8 + j;
            bf[j] = *(const float2*)&sb[((nt*4 + ks)*32 + lane)*2];
        }
        #pragma unroll
        for (int i = 0; i < 2; i++)
            #pragma unroll
            for (int j = 0; j < 8; j++)
                mma_tf32(acc[i][j], af[i], bf[j]);
    }
}

// ---------------- generic GEMM: C = act(A @ Wt^T + bias) -------------------
template<int ACT, int FIN>
__global__ void __launch_bounds__(256) k_mma(
    const float* __restrict__ A, const float* __restrict__ Wt,
    const float* __restrict__ bias, float* __restrict__ C,
    int K, int ldc, long sA, long sW, long sB, long sC, int bstride)
{
    extern __shared__ float smem[];
    float* sa0 = smem;         float* sa1 = smem + 4096;
    float* sb0 = smem + 8192;  float* sb1 = smem + 12288;
    int z = blockIdx.z;
    int bm = blockIdx.y*128, bn = blockIdx.x*128;
    A    += (size_t)z*sA;
    Wt   += (size_t)z*sW;
    bias += (size_t)z*sB + (size_t)(bm >> 10)*bstride;
    C    += (size_t)z*sC;
    int tid = threadIdx.x, wid = tid >> 5, lane = tid & 31;
    int g = lane >> 2, tig = lane & 3;
    int wm = (wid & 3)*32, wn = (wid >> 2)*64;

    float acc[2][8][4];
    #pragma unroll
    for (int i = 0; i < 2; i++)
        #pragma unroll
        for (int j = 0; j < 8; j++)
            #pragma unroll
            for (int q = 0; q < 4; q++) acc[i][j][q] = 0.f;

    int nch = K >> 5;
    float4 ra[4], rb[4];
    gload(A, Wt, bm, bn, K, 0, tid, ra, rb);
    gscatter(ra, rb, sa0, sb0, tid);
    __syncthreads();
    for (int c = 0; c < nch; c++) {
        int buf = c & 1;
        if (c + 1 < nch) gload(A, Wt, bm, bn, K, (c+1)*32, tid, ra, rb);
        gmma(buf ? sa1 : sa0, buf ? sb1 : sb0, wid, lane, acc);
        if (c + 1 < nch) gscatter(ra, rb, buf ? sa0 : sa1, buf ? sb0 : sb1, tid);
        __syncthreads();
    }

    #pragma unroll
    for (int i = 0; i < 2; i++) {
        int r0 = bm + wm + i*16 + g;
        #pragma unroll
        for (int j = 0; j < 8; j++) {
            int col = bn + wn + j*8 + tig*2;
            float b0 = bias[col], b1 = bias[col+1];
            float v0 = acc[i][j][0] + b0, v1 = acc[i][j][1] + b1;
            float v2 = acc[i][j][2] + b0, v3 = acc[i][j][3] + b1;
            if (ACT) { v0 = gelu_f(v0); v1 = gelu_f(v1); v2 = gelu_f(v2); v3 = gelu_f(v3); }
            if (FIN) {
                v0 = g_zpart[(size_t)r0*ldc + col]       + 0.3f*v0;
                v1 = g_zpart[(size_t)r0*ldc + col + 1]   + 0.3f*v1;
                v2 = g_zpart[(size_t)(r0+8)*ldc + col]   + 0.3f*v2;
                v3 = g_zpart[(size_t)(r0+8)*ldc + col+1] + 0.3f*v3;
            }
            *(float2*)(C + (size_t)r0*ldc + col)     = make_float2(v0, v1);
            *(float2*)(C + (size_t)(r0+8)*ldc + col) = make_float2(v2, v3);
        }
    }
}

// ---------------- permute weffT chunks into fragment layout ----------------
// block = (k, bnb, c8) ; chunk = rows bnb*128..+127, cols c8*32..+31 of weffT_k
__global__ void k_permW()
{
    int bx = blockIdx.x;
    int k = bx >> 4, rem = bx & 15, bnb = rem >> 3, c8 = rem & 7;
    int tid = threadIdx.x;
    const float* src = g_weffT + (size_t)k*65536;
    float* dst = g_weffP + ((size_t)(k*2 + bnb)*8 + c8)*4096;
    #pragma unroll
    for (int q = 0; q < 4; q++) {
        int f = tid + q*256;
        int row = f >> 3, seg = f & 7;
        float4 v = *(const float4*)(src + (size_t)(bnb*128 + row)*256 + c8*32 + seg*4);
        int ks = seg >> 1, posK = seg & 1;
        int bbase = (((row >> 3)*4 + ks)*32 + (row & 7)*4)*2 + posK;
        float bv[4] = {v.x, v.y, v.z, v.w};
        #pragma unroll
        for (int e = 0; e < 4; e++) dst[bbase + e*2] = tf32r(bv[e]);
    }
}

// ---------------- permute wp1T halves into fragment layout -----------------
__global__ void k_permP()
{
    int bx = blockIdx.x;
    int k = bx >> 1, h = bx & 1;
    int tid = threadIdx.x;
    const float* src = g_wp1T + (size_t)k*8192;
    float* dst = g_wp1P + (size_t)(k*2 + h)*4096;
    #pragma unroll
    for (int q = 0; q < 4; q++) {
        int f = tid + q*256;
        int row = f >> 3, seg = f & 7;
        float4 v = *(const float4*)(src + (size_t)(h*128 + row)*32 + seg*4);
        int ks = seg >> 1, posK = seg & 1;
        int bbase = (((row >> 3)*4 + ks)*32 + (row & 7)*4)*2 + posK;
        float bv[4] = {v.x, v.y, v.z, v.w};
        #pragma unroll
        for (int e = 0; e < 4; e++) dst[bbase + e*2] = tf32r(bv[e]);
    }
}

// ---------------- fully fused: hf1 = gelu(Σ_k gelu(xc_k@wp1T_k^T + ckb)@weffT_k + bconst)
// p1 tiles regenerated in SMEM; weights streamed via cp.async double buffer.
__global__ void __launch_bounds__(256) k_ff()
{
    extern __shared__ float smem[];
    float* saA = smem;             // 16384 floats (4 A-fragment chunks of p1 half)
    float* sxc = smem + 16384;     // 4096 (xc A-chunk)
    float* swp = smem + 20480;     // 8192 (wp1P halves)
    float* swf = smem + 28672;     // 8192 (weffP chunks, dbl buf)
    int bm = blockIdx.y*128, bnb = blockIdx.x, bn = bnb*128;
    int b  = bm >> 10;
    int tid = threadIdx.x, wid = tid >> 5, lane = tid & 31;
    int g = lane >> 2, tig = lane & 3;
    int wm = (wid & 3)*32, wn = (wid >> 2)*64;
    uint32_t swp_u = smem_u32(swp), swf_u = smem_u32(swf);

    float ACC[2][8][4];
    #pragma unroll
    for (int i = 0; i < 2; i++)
        #pragma unroll
        for (int j = 0; j < 8; j++)
            #pragma unroll
            for (int q = 0; q < 4; q++) ACC[i][j][q] = 0.f;

    // chunk t = k*8 + h*4 + cc, buffer t&1
    auto issue_chunk = [&](int t) {
        const float* src = g_weffP + ((size_t)((t >> 3)*2 + bnb)*8 + (t & 7))*4096 + tid*16;
        uint32_t dst = swf_u + ((uint32_t)(t & 1)*4096 + tid*16)*4;
        #pragma unroll
        for (int q = 0; q < 4; q++) CP_ASYNC16(dst + q*16, src + q*4);
    };
    auto issue_swp = [&](int k) {
        const float* src = g_wp1P + (size_t)k*8192 + tid*32;
        uint32_t dst = swp_u + (uint32_t)tid*32*4;
        #pragma unroll
        for (int q = 0; q < 8; q++) CP_ASYNC16(dst + q*16, src + q*4);
    };

    issue_swp(0);
    issue_chunk(0);
    CP_COMMIT();

    int t = 0;
    const int TMAX = KF*8;
    for (int k = 0; k < KF; k++) {
        __syncthreads();     // sxc readers (gemm1 of k-1) done
        // xc A-chunk scatter (data-dependent; manual)
        {
            const float* Axc = g_xc + ((size_t)k*RTOT + bm)*32;
            #pragma unroll
            for (int q = 0; q < 4; q++) {
                int f = tid + q*256;
                int row = f >> 3, seg = f & 7;
                float4 v = *(const float4*)(Axc + (size_t)row*32 + seg*4);
                int ks = seg >> 1, posK = seg & 1;
                int abase = (((row >> 4)*4 + ks)*32 + (row & 7)*4)*4 + posK*2 + ((row >> 3) & 1);
                float av[4] = {v.x, v.y, v.z, v.w};
                #pragma unroll
                for (int e = 0; e < 4; e++) sxc[abase + e*4] = tf32r(av[e]);
            }
        }
        CP_WAIT0();
        __syncthreads();     // swp(k), chunk t, sxc all visible
        #pragma unroll
        for (int h = 0; h < 2; h++) {
            // GEMM1: p1 half = xc @ wp1T_h
            float a1[2][8][4];
            #pragma unroll
            for (int i = 0; i < 2; i++)
                #pragma unroll
                for (int j = 0; j < 8; j++)
                    #pragma unroll
                    for (int q = 0; q < 4; q++) a1[i][j][q] = 0.f;
            gmma(sxc, swp + h*4096, wid, lane, a1);
            __syncthreads();   // saA readers (prev chunks' gmma) done
            const float* ck = g_ckb + (size_t)(k*BB + b)*DD + h*128;
            #pragma unroll
            for (int i = 0; i < 2; i++)
                #pragma unroll
                for (int j = 0; j < 8; j++)
                    #pragma unroll
                    for (int q = 0; q < 4; q++) {
                        int row  = wm + i*16 + g + ((q >> 1) ? 8 : 0);
                        int kcol = wn + j*8 + tig*2 + (q & 1);
                        float val = gelu_f(a1[i][j][q] + ck[kcol]);
                        int cc = kcol >> 5, kk = kcol & 31;
                        int idx = cc*4096
                                + (((row >> 4)*4 + (kk >> 3))*32 + (row & 7)*4 + (kk & 3))*4
                                + ((kk >> 2) & 1)*2 + ((row >> 3) & 1);
                        saA[idx] = tf32r(val);
                    }
            __syncthreads();   // saA visible
            #pragma unroll
            for (int cc = 0; cc < 4; cc++) {
                if (cc > 0 || h > 0) {
                    CP_WAIT0();
                    __syncthreads();   // chunk t visible; prior gmma done
                }
                bool iss = false;
                if (t + 1 < TMAX) { issue_chunk(t + 1); iss = true; }
                if ((t & 7) == 6 && k + 1 < KF) { issue_swp(k + 1); iss = true; }
                if (iss) CP_COMMIT();
                gmma(saA + cc*4096, swf + (t & 1)*4096, wid, lane, ACC);
                t++;
            }
        }
    }

    // epilogue
    #pragma unroll
    for (int i = 0; i < 2; i++) {
        int r0 = bm + wm + i*16 + g;
        #pragma unroll
        for (int j = 0; j < 8; j++) {
            int col = bn + wn + j*8 + tig*2;
            float b0 = g_bconst[col], b1 = g_bconst[col+1];
            float2 lo = make_float2(gelu_f(ACC[i][j][0] + b0), gelu_f(ACC[i][j][1] + b1));
            float2 hi = make_float2(gelu_f(ACC[i][j][2] + b0), gelu_f(ACC[i][j][3] + b1));
            *(float2*)(g_hf1 + (size_t)r0*256 + col)     = lo;
            *(float2*)(g_hf1 + (size_t)(r0+8)*256 + col) = hi;
        }
    }
}

// ---------------- weight transpose [K,N] -> [N,K] --------------------------
__global__ void k_tr(const float* __restrict__ W, float* __restrict__ WT, int K, int N)
{
    __shared__ float tile[32][33];
    int z = blockIdx.z;
    W  += (size_t)z*K*N;
    WT += (size_t)z*K*N;
    int k0 = blockIdx.y*32, n0 = blockIdx.x*32;
    int tx = threadIdx.x, ty = threadIdx.y;
    for (int i = ty; i < 32; i += 8) tile[i][tx] = W[(size_t)(k0+i)*N + n0+tx];
    __syncthreads();
    for (int i = ty; i < 32; i += 8) WT[(size_t)(n0+i)*K + k0+tx] = tile[tx][i];
}

// ---------------- k_uv partials: wp1 fold, split over e ---------------------
__global__ void k_uv1(const float* __restrict__ W, const float* __restrict__ W1)
{
    int bx = blockIdx.x;
    int k = bx >> 2, eq = bx & 3;
    int o = threadIdx.x;
    __shared__ float Ws[CC*DD];
    for (int i = o; i < CC*DD; i += 256) Ws[i] = W[i];
    __syncthreads();
    float acc[32];
    #pragma unroll
    for (int c = 0; c < 32; c++) acc[c] = 0.f;
    const float* w1 = W1 + (size_t)k*512*DD;
    for (int e = eq*64; e < eq*64 + 64; e++) {
        float u = w1[(size_t)e*DD + o];
        float v = w1[(size_t)(256+e)*DD + o];
        #pragma unroll
        for (int c = 0; c < 16; c++) {
            acc[c]      += Ws[c*DD + e]*u;
            acc[16 + c] += Ws[c*DD + e]*v;
        }
    }
    float* dst = g_uvp + ((size_t)(k*4 + eq)*DD + o)*32;
    #pragma unroll
    for (int c = 0; c < 32; c++) dst[c] = acc[c];
}
__global__ void k_uv2()
{
    int k = blockIdx.x, o = threadIdx.x;
    float* dst = g_wp1T + ((size_t)k*DD + o)*32;
    #pragma unroll
    for (int c = 0; c < 32; c++) {
        float s = 0.f;
        #pragma unroll
        for (int eq = 0; eq < 4; eq++)
            s += g_uvp[((size_t)(k*4 + eq)*DD + o)*32 + c];
        dst[c] = s;
    }
}

// ---------------- te DFT + te_att ------------------------------------------
__global__ void k_tedft(const float* __restrict__ in_proj_b)
{
    int b = blockIdx.x, e = threadIdx.x;
    float teb[PP];
    #pragma unroll
    for (int p = 0; p < PP; p++)
        teb[p] = g_time_emb[(b*PP + p)*DD + e] + in_proj_b[e];
    float ta = 0.f;
    #pragma unroll
    for (int p = 0; p < PP; p++) ta += g_att[b*PP + p]*teb[p];
    g_teatt[b*DD + e] = ta;
    for (int k = 0; k < KF; k++) {
        float re = 0.f, im = 0.f;
        #pragma unroll
        for (int p = 0; p < PP; p++) {
            re += teb[p]*g_tw[k*PP + p];
            im -= teb[p]*g_tw[KF*PP + k*PP + p];
        }
        g_tere[(k*BB + b)*DD + e] = re;
        g_teim[(k*BB + b)*DD + e] = im;
    }
}

// ---------------- c_kb[o] = b1_k[o] + Σ_e tere*W1_k[e][o] + teim*W1_k[256+e][o]
__global__ void k_ckb(const float* __restrict__ W1, const float* __restrict__ b1)
{
    int k = blockIdx.x, b = blockIdx.y, o = threadIdx.x;
    __shared__ float sre[DD], sim[DD];
    sre[o] = g_tere[(k*BB + b)*DD + o];
    sim[o] = g_teim[(k*BB + b)*DD + o];
    __syncthreads();
    float acc = b1[(size_t)k*DD + o];
    const float* w1 = W1 + (size_t)k*512*DD;
    for (int e = 0; e < 256; e++)
        acc += sre[e]*w1[(size_t)e*DD + o] + sim[e]*w1[(size_t)(256+e)*DD + o];
    g_ckb[(k*BB + b)*DD + o] = acc;
}

// ---------------- folded bias: bconst = comb_b1 + Σ b2·Wc1 (two-stage) -----
__global__ void k_bc1(const float* __restrict__ sfe_b2,
                      const float* __restrict__ comb_w1)
{
    int k = blockIdx.x, j = threadIdx.x;
    float s = 0.f;
    for (int i = k*256; i < k*256 + 256; i++)
        s += sfe_b2[i]*comb_w1[(size_t)i*256 + j];
    g_bcp[k*DD + j] = s;
}
__global__ void k_bc2(const float* __restrict__ comb_b1)
{
    int j = threadIdx.x;
    float s = comb_b1[j];
    #pragma unroll
    for (int k = 0; k < KF; k++) s += g_bcp[k*DD + j];
    g_bconst[j] = s;
}

// ---------------- tiny init ------------------------------------------------
__global__ void k_init(const float* __restrict__ pe_w1, const float* __restrict__ pe_b1,
                       const float* __restrict__ pe_w2, const float* __restrict__ pe_b2,
                       const float* __restrict__ pool_param)
{
    int t = threadIdx.x;
    for (int idx = t; idx < KF*PP; idx += blockDim.x) {
        int k = idx / PP, p = idx % PP;
        double ang = 2.0*M_PI*(double)(k*p)/24.0;
        g_tw[idx]        = (float)cos(ang);
        g_tw[KF*PP+idx]  = (float)sin(ang);
    }
    if (t < 2*PP) {
        int kk = t / PP, p = t % PP;
        double period = (kk == 0) ? 24.0 : 72.0;
        double ph = 2.0*M_PI*(double)p/period;
        float s = (float)sin(ph), c = (float)cos(ph);
        float hid[64];
        #pragma unroll
        for (int o = 0; o < 64; o++) {
            float v = s*pe_w1[kk*128 + o] + c*pe_w1[kk*128 + 64 + o] + pe_b1[kk*64 + o];
            hid[o] = gelu_f(v);
        }
        for (int q = 0; q < 64; q++) {
            float acc = pe_b2[kk*64 + q];
            #pragma unroll
            for (int o = 0; o < 64; o++) acc += hid[o]*pe_w2[kk*4096 + o*64 + q];
            g_periodic[p*128 + kk*64 + q] = acc;
        }
    }
    if (t == 0) {
        float mx = -1e30f;
        for (int p = 0; p < PP; p++) mx = fmaxf(mx, pool_param[p]);
        float se = 0.f, e[PP];
        for (int p = 0; p < PP; p++) { e[p] = expf(pool_param[p]-mx); se += e[p]; }
        for (int p = 0; p < PP; p++) g_base_att[p] = e[p]/se;
    }
}

// ---------------- spatial mean -> noise; assemble time_emb ----------------
__global__ void k_noise(const float* __restrict__ x, const float* __restrict__ noise_w,
                        const float* __restrict__ noise_b)
{
    int bp = blockIdx.x;
    int t  = threadIdx.x;
    __shared__ float partial[256];
    __shared__ float mean[CC];
    const float* xb = x + (size_t)bp*NN*CC;
    float acc = 0.f;
    for (int i = t; i < NN*CC; i += 256) acc += xb[i];
    partial[t] = acc;
    __syncthreads();
    if (t < CC) {
        float s = 0.f;
        for (int j = t; j < 256; j += CC) s += partial[j];
        mean[t] = s*(1.f/(float)NN);
    }
    __syncthreads();
    if (t < 128) {
        float nz = noise_b[t];
        #pragma unroll
        for (int c = 0; c < CC; c++) nz += mean[c]*noise_w[c*128 + t];
        g_time_emb[bp*DD + 128 + t] = nz;
        g_time_emb[bp*DD + t]       = g_periodic[(bp % PP)*128 + t];
    }
}

__global__ void k_timevec(float* __restrict__ out)
{
    int b = blockIdx.x, e = threadIdx.x;
    float s = 0.f;
    for (int p = 0; p < PP; p++) s += g_time_emb[(b*PP + p)*DD + e];
    out[(size_t)BB*NN*DD + b*DD + e] = s*(1.f/24.f);
}

// ---------------- x DFT + attention-weighted x -----------------------------
__global__ void __launch_bounds__(256) k_xdft(const float* __restrict__ x)
{
    __shared__ float twc[KF*PP], tws[KF*PP], atts[PP];
    int tid = threadIdx.x;
    int r = blockIdx.x*16 + (tid >> 4);
    int c = tid & 15;
    int b = r >> 10, n = r & 1023;
    for (int i = tid; i < KF*PP; i += 256) { twc[i] = g_tw[i]; tws[i] = g_tw[KF*PP + i]; }
    if (tid < PP) atts[tid] = g_att[b*PP + tid];
    __syncthreads();
    float re[KF], im[KF], xa = 0.f;
    #pragma unroll
    for (int k = 0; k < KF; k++) { re[k] = 0.f; im[k] = 0.f; }
    #pragma unroll
    for (int p = 0; p < PP; p++) {
        float xv = x[((size_t)(b*PP + p)*NN + n)*CC + c];
        xa += atts[p]*xv;
        #pragma unroll
        for (int k = 0; k < KF; k++) {
            re[k] += twc[k*PP + p]*xv;
            im[k] -= tws[k*PP + p]*xv;
        }
    }
    g_xatt[(size_t)r*CC + c] = xa;
    #pragma unroll
    for (int k = 0; k < KF; k++) {
        g_xc[((size_t)k*RTOT + r)*32 + c]      = re[k];
        g_xc[((size_t)k*RTOT + r)*32 + 16 + c] = im[k];
    }
}

// ---------------- zpart = xatt @ W + te_att --------------------------------
__global__ void k_zpart(const float* __restrict__ w)
{
    int blk = blockIdx.x;
    int r0 = blk*64;
    int b = r0 >> 10;
    int t = threadIdx.x;
    __shared__ float Ws[CC*DD];
    __shared__ float xs[64*CC];
    __shared__ float tb[DD];
    for (int i = t; i < CC*DD; i += 256) Ws[i] = w[i];
    tb[t] = g_teatt[b*DD + t];
    for (int i = t; i < 64*CC; i += 256) xs[i] = g_xatt[(size_t)r0*CC + i];
    __syncthreads();
    float* zp = g_zpart + (size_t)r0*DD;
    for (int nn = 0; nn < 64; nn++) {
        float acc = tb[t];
        #pragma unroll
        for (int c = 0; c < CC; c++) acc += xs[nn*CC + c]*Ws[c*DD + t];
        zp[(size_t)nn*DD + t] = acc;
    }
}

// ---------------- gating: lagged diffs over raw x -------------------------
__device__ __forceinline__ float xr_val(const float* __restrict__ xb, int p, int i)
{
    float xp = xb[(size_t)p*16384 + i];
    float base;
    if (p <= 1) base = xb[i];
    else base = (xb[(size_t)(p-2)*16384 + i] + xb[(size_t)(p-1)*16384 + i] + xp)*(1.f/3.f);
    return xp - base;
}

__global__ void k_gd(const float* __restrict__ x)
{
    int bp = blockIdx.x;
    int b = bp / PP, p = bp % PP;
    int t = threadIdx.x;
    const float* xb = x + (size_t)b*PP*16384;
    float s0=0.f, s1=0.f, s2=0.f, s3=0.f;
    for (int i = t; i < 16384; i += 256) {
        float xr_p = xr_val(xb, p, i);
        if (p >= 1) s0 += fabsf(xr_p - xr_val(xb, p-1, i));
        if (p >= 2) s1 += fabsf(xr_p - xr_val(xb, p-2, i));
        if (p >= 4) s2 += fabsf(xr_p - xr_val(xb, p-4, i));
        if (p >= 6) s3 += fabsf(xr_p - xr_val(xb, p-6, i));
    }
    __shared__ float red[4][256];
    red[0][t]=s0; red[1][t]=s1; red[2][t]=s2; red[3][t]=s3;
    __syncthreads();
    if (t < 4) {
        float ss = 0.f;
        for (int j = 0; j < 256; j++) ss += red[t][j];
        g_dd[(b*4 + t)*PP + p] = ss*(1.f/16384.f);
    }
}

__global__ void k_att()
{
    __shared__ float sp[BB][4][PP];
    int t = threadIdx.x;
    if (t < 32) {
        int b = t >> 2, l = t & 3;
        float dv[PP], srt[PP];
        for (int p = 0; p < PP; p++) dv[p] = g_dd[(b*4 + l)*PP + p];
        for (int p = 0; p < PP; p++) srt[p] = dv[p];
        isort(srt, PP);
        float med = srt[11];
        for (int p = 0; p < PP; p++) srt[p] = fabsf(dv[p] - med);
        isort(srt, PP);
        float mad = srt[11];
        float denom = mad*1.4826f + 1e-6f;
        for (int p = 0; p < PP; p++) {
            float zz = (dv[p] - med)/denom;
            sp[b][l][p] = softplus_f(zz);
        }
    }
    __syncthreads();
    if (t < BB) {
        int b = t;
        float g[PP];
        for (int p = 0; p < PP; p++)
            g[p] = 0.25f*(sp[b][0][p] + sp[b][1][p] + sp[b][2][p] + sp[b][3][p]);
        float c = g[0];
        for (int p = 1; p < PP; p++) { c = 0.6f*c + 0.4f*g[p]; g[p] = c; }
        float gm = 0.f;
        for (int p = 0; p < PP; p++) gm += g[p];
        gm *= (1.f/24.f);
        float logit[PP], mx = -1e30f;
        for (int p = 0; p < PP; p++) {
            float gg = 1.f/(1.f + expf(-1.5f*(g[p] - gm)));
            logit[p] = g_base_att[p]*(1.f + gg);
            mx = fmaxf(mx, logit[p]);
        }
        float se = 0.f;
        for (int p = 0; p < PP; p++) { logit[p] = expf(logit[p] - mx); se += logit[p]; }
        for (int p = 0; p < PP; p++) g_att[b*PP + p] = logit[p]/se;
    }
}

// ---------------- launch ---------------------------------------------------
extern "C" void kernel_launch(void* const* d_in, const int* in_sizes, int n_in,
                              void* d_out, int out_size)
{
    const float* x         = (const float*)d_in[0];
    const float* in_proj_w = (const float*)d_in[1];
    const float* in_proj_b = (const float*)d_in[2];
    const float* pe_w1     = (const float*)d_in[3];
    const float* pe_b1     = (const float*)d_in[4];
    const float* pe_w2     = (const float*)d_in[5];
    const float* pe_b2     = (const float*)d_in[6];
    const float* noise_w   = (const float*)d_in[7];
    const float* noise_b   = (const float*)d_in[8];
    const float* sfe_w1    = (const float*)d_in[9];
    const float* sfe_b1    = (const float*)d_in[10];
    const float* sfe_w2    = (const float*)d_in[11];
    const float* sfe_b2    = (const float*)d_in[12];
    const float* comb_w1   = (const float*)d_in[13];
    const float* comb_b1   = (const float*)d_in[14];
    const float* comb_w2   = (const float*)d_in[15];
    const float* comb_b2   = (const float*)d_in[16];
    const float* pool_param= (const float*)d_in[17];
    float* out = (float*)d_out;

    float *p_hf1, *p_wc1T, *p_weffT, *p_wc2T, *p_zero;
    cudaGetSymbolAddress((void**)&p_hf1,   g_hf1);
    cudaGetSymbolAddress((void**)&p_wc1T,  g_wc1T);
    cudaGetSymbolAddress((void**)&p_weffT, g_weffT);
    cudaGetSymbolAddress((void**)&p_wc2T,  g_wc2T);
    cudaGetSymbolAddress((void**)&p_zero,  g_zero);

    const int SMEM  = 16384*4;     // 64 KB for k_mma
    const int SMEMF = 36864*4;     // 144 KB for k_ff
    cudaFuncSetAttribute(k_mma<0,0>, cudaFuncAttributeMaxDynamicSharedMemorySize, SMEM);
    cudaFuncSetAttribute(k_mma<0,1>, cudaFuncAttributeMaxDynamicSharedMemorySize, SMEM);
    cudaFuncSetAttribute(k_ff,       cudaFuncAttributeMaxDynamicSharedMemorySize, SMEMF);

    // scalars / gating / embeddings
    k_init<<<1, 256>>>(pe_w1, pe_b1, pe_w2, pe_b2, pool_param);
    k_gd<<<BB*PP, 256>>>(x);
    k_att<<<1, 32>>>();
    k_noise<<<BB*PP, 256>>>(x, noise_w, noise_b);
    k_tedft<<<BB, 256>>>(in_proj_b);
    k_timevec<<<BB, 256>>>(out);

    // x-side folds
    k_xdft<<<RTOT/16, 256>>>(x);
    k_zpart<<<RTOT/64, 256>>>(in_proj_w);

    // weight prep
    dim3 trb(32, 8);
    k_uv1<<<KF*4, 256>>>(in_proj_w, sfe_w1);
    k_uv2<<<KF, 256>>>();
    k_ckb<<<dim3(KF, BB), 256>>>(sfe_w1, sfe_b1);
    k_tr<<<dim3(256/32, 256/32, KF), trb>>>(comb_w1, p_wc1T, 256, 256);
    k_tr<<<dim3(256/32, 256/32, 1),  trb>>>(comb_w2, p_wc2T, 256, 256);
    k_mma<0,0><<<dim3(2, 2, KF), 256, SMEM>>>(p_wc1T, sfe_w2, p_zero, p_weffT,
        256, 256, 65536L, 65536L, 0L, 65536L, 0);
    k_permW<<<KF*16, 256>>>();
    k_permP<<<KF*2, 256>>>();
    k_bc1<<<KF, 256>>>(sfe_b2, comb_w1);
    k_bc2<<<1, 256>>>(comb_b1);

    // fused sfe1 + sfe2·comb1: hf1
    k_ff<<<dim3(2, 64), 256, SMEMF>>>();
    // out = zpart + 0.3*(hf1 @ Wc2 + b2)
    k_mma<0,1><<<dim3(2, 64), 256, SMEM>>>(p_hf1, p_wc2T, comb_b2, out,
        256, 256, 0L, 0L, 0L, 0L, 0);
}